// round 1
// baseline (speedup 1.0000x reference)
#include <cuda_runtime.h>
#include <cuda_bf16.h>
#include <math.h>

#define NN 2048          // nodes
#define NH 8             // heads
#define ALPHA 0.2f
#define NNZ_CAP (2048*128)
#define HID_MAX 512

// ---------------- scratch (static device allocations) ----------------
__device__ int   g_deg[NN];
__device__ int   g_rowptr[NN + 1];
__device__ int   g_colidx[NNZ_CAP];
__device__ float g_h[NH * NN * HID_MAX];        // per-head projected features
__device__ float g_hcat[NN * NH * HID_MAX];     // concat heads
__device__ float g_s1[NH * NN];
__device__ float g_s2[NH * NN];
__device__ float g_att[(size_t)NH * NNZ_CAP];
__device__ float g_ho[NN * HID_MAX];
__device__ float g_o1[NN];
__device__ float g_o2[NN];
__device__ float g_xb0[NN * HID_MAX];
__device__ float g_xb1[NN * HID_MAX];

// ---------------- CSR build ----------------
__global__ void csr_count(const float* __restrict__ adj, int* __restrict__ deg) {
    int row = blockIdx.x * (blockDim.x >> 5) + (threadIdx.x >> 5);
    if (row >= NN) return;
    int lane = threadIdx.x & 31;
    const float* r = adj + (size_t)row * NN;
    int cnt = 0;
    for (int c0 = 0; c0 < NN; c0 += 32) {
        float v = r[c0 + lane];
        unsigned m = __ballot_sync(0xffffffffu, v > 0.f);
        cnt += __popc(m);
    }
    if (lane == 0) deg[row] = cnt;
}

__global__ void csr_scan(const int* __restrict__ deg, int* __restrict__ rowptr) {
    __shared__ int s[1024];
    int t = threadIdx.x;                  // 1024 threads
    int d0 = deg[2 * t], d1 = deg[2 * t + 1];
    s[t] = d0 + d1;
    __syncthreads();
    for (int off = 1; off < 1024; off <<= 1) {
        int v = s[t];
        int add = (t >= off) ? s[t - off] : 0;
        __syncthreads();
        s[t] = v + add;
        __syncthreads();
    }
    int excl = (t > 0) ? s[t - 1] : 0;    // exclusive sum of pairs
    rowptr[2 * t]     = excl;
    rowptr[2 * t + 1] = excl + d0;
    if (t == 1023) rowptr[NN] = s[1023];
}

__global__ void csr_fill(const float* __restrict__ adj, const int* __restrict__ rowptr,
                         int* __restrict__ colidx) {
    int row = blockIdx.x * (blockDim.x >> 5) + (threadIdx.x >> 5);
    if (row >= NN) return;
    int lane = threadIdx.x & 31;
    const float* r = adj + (size_t)row * NN;
    int pos = rowptr[row];
    for (int c0 = 0; c0 < NN; c0 += 32) {
        float v = r[c0 + lane];
        unsigned m = __ballot_sync(0xffffffffu, v > 0.f);
        if (v > 0.f) {
            int off = __popc(m & ((1u << lane) - 1u));
            colidx[pos + off] = c0 + lane;
        }
        pos += __popc(m);
    }
}

// ---------------- tiled fp32 GEMM: C = A(MxK) * B(KxN), row-major ----------------
// BM=BN=64, BK=16, 16x16 threads, 4x4 micro-tile. Requires M%64==0, N%64==0, K%16==0.
__global__ void sgemm64(const float* __restrict__ A, const float* __restrict__ B,
                        float* __restrict__ C, int M, int Nn, int K,
                        long sA, long sB, long sC) {
    A += (long)blockIdx.z * sA;
    B += (long)blockIdx.z * sB;
    C += (long)blockIdx.z * sC;
    __shared__ float As[16][64];
    __shared__ float Bs[16][64];
    int tx = threadIdx.x, ty = threadIdx.y;
    int tid = ty * 16 + tx;
    int rowBase = blockIdx.y * 64;
    int colBase = blockIdx.x * 64;

    // A tile loader indices: m = tid/4, k chunk = (tid%4)*4
    int am = tid >> 2;
    int ak = (tid & 3) << 2;
    // B tile loader: k = tid/16, n chunk = (tid%16)*4
    int bk = tid >> 4;
    int bn = (tid & 15) << 2;

    float c[4][4];
#pragma unroll
    for (int i = 0; i < 4; i++)
#pragma unroll
        for (int j = 0; j < 4; j++) c[i][j] = 0.f;

    for (int k0 = 0; k0 < K; k0 += 16) {
        float4 av = *(const float4*)&A[(size_t)(rowBase + am) * K + k0 + ak];
        As[ak + 0][am] = av.x;
        As[ak + 1][am] = av.y;
        As[ak + 2][am] = av.z;
        As[ak + 3][am] = av.w;
        *(float4*)&Bs[bk][bn] = *(const float4*)&B[(size_t)(k0 + bk) * Nn + colBase + bn];
        __syncthreads();
#pragma unroll
        for (int k = 0; k < 16; k++) {
            float4 a = *(const float4*)&As[k][ty << 2];
            float4 b = *(const float4*)&Bs[k][tx << 2];
            c[0][0] += a.x * b.x; c[0][1] += a.x * b.y; c[0][2] += a.x * b.z; c[0][3] += a.x * b.w;
            c[1][0] += a.y * b.x; c[1][1] += a.y * b.y; c[1][2] += a.y * b.z; c[1][3] += a.y * b.w;
            c[2][0] += a.z * b.x; c[2][1] += a.z * b.y; c[2][2] += a.z * b.z; c[2][3] += a.z * b.w;
            c[3][0] += a.w * b.x; c[3][1] += a.w * b.y; c[3][2] += a.w * b.z; c[3][3] += a.w * b.w;
        }
        __syncthreads();
    }
#pragma unroll
    for (int i = 0; i < 4; i++) {
        float4 v = make_float4(c[i][0], c[i][1], c[i][2], c[i][3]);
        *(float4*)&C[(size_t)(rowBase + (ty << 2) + i) * Nn + colBase + (tx << 2)] = v;
    }
}

// ---------------- s1/s2 dot products (warp per (head,node)) ----------------
__global__ void dot_s(const float* __restrict__ h, const float* __restrict__ a,
                      float* __restrict__ s1, float* __restrict__ s2, int hid, int total) {
    int w = (blockIdx.x * blockDim.x + threadIdx.x) >> 5;
    if (w >= total) return;
    int lane = threadIdx.x & 31;
    int head = w / NN;
    const float* hp = h + (size_t)w * hid;
    const float* a1 = a + (size_t)head * 2 * hid;
    const float* a2 = a1 + hid;
    float v1 = 0.f, v2 = 0.f;
    for (int d = lane; d < hid; d += 32) {
        float x = hp[d];
        v1 += x * a1[d];
        v2 += x * a2[d];
    }
#pragma unroll
    for (int o = 16; o; o >>= 1) {
        v1 += __shfl_xor_sync(0xffffffffu, v1, o);
        v2 += __shfl_xor_sync(0xffffffffu, v2, o);
    }
    if (lane == 0) { s1[w] = v1; s2[w] = v2; }
}

// ---------------- masked softmax over neighbor lists (warp per (head,row)) ----------------
__global__ void att_softmax(const int* __restrict__ rowptr, const int* __restrict__ colidx,
                            const float* __restrict__ s1, const float* __restrict__ s2,
                            float* __restrict__ att, int total) {
    int w = (blockIdx.x * blockDim.x + threadIdx.x) >> 5;
    if (w >= total) return;
    int lane = threadIdx.x & 31;
    int head = w / NN;
    int i = w - head * NN;
    int b = rowptr[i], e = rowptr[i + 1];
    const float* s2h = s2 + (size_t)head * NN;
    float si = s1[w];
    float m = -1e30f;
    for (int k = b + lane; k < e; k += 32) {
        float v = si + s2h[colidx[k]];
        v = v > 0.f ? v : ALPHA * v;
        m = fmaxf(m, v);
    }
#pragma unroll
    for (int o = 16; o; o >>= 1) m = fmaxf(m, __shfl_xor_sync(0xffffffffu, m, o));
    float sum = 0.f;
    float* ah = att + (size_t)head * NNZ_CAP;
    for (int k = b + lane; k < e; k += 32) {
        float v = si + s2h[colidx[k]];
        v = v > 0.f ? v : ALPHA * v;
        float ex = expf(v - m);
        ah[k] = ex;
        sum += ex;
    }
#pragma unroll
    for (int o = 16; o; o >>= 1) sum += __shfl_xor_sync(0xffffffffu, sum, o);
    float inv = 1.f / sum;
    for (int k = b + lane; k < e; k += 32) ah[k] *= inv;
}

// ---------------- sparse att @ h with ELU epilogue (block per (row,head)) ----------------
__device__ __forceinline__ float elu1(float x) { return x > 0.f ? x : expm1f(x); }

__global__ void spmm_elu(const int* __restrict__ rowptr, const int* __restrict__ colidx,
                         const float* __restrict__ att, const float* __restrict__ h,
                         float* __restrict__ out, int hid, int out_stride) {
    int i = blockIdx.x, head = blockIdx.y;
    int tid = threadIdx.x;                    // 128
    int b = rowptr[i], e = rowptr[i + 1];
    const float* hb = h + (size_t)head * NN * hid;
    const float* av = att + (size_t)head * NNZ_CAP;
    int nt = hid >> 7;                        // hid in {128,256,384,512}
    float a0 = 0.f, a1 = 0.f, a2 = 0.f, a3 = 0.f;
    for (int k = b; k < e; k++) {
        int j = colidx[k];
        float a = __ldg(&av[k]);
        const float* hr = hb + (size_t)j * hid;
        a0 += a * hr[tid];
        if (nt > 1) a1 += a * hr[tid + 128];
        if (nt > 2) a2 += a * hr[tid + 256];
        if (nt > 3) a3 += a * hr[tid + 384];
    }
    float* op = out + (size_t)i * out_stride + (size_t)head * hid;
    op[tid] = elu1(a0);
    if (nt > 1) op[tid + 128] = elu1(a1);
    if (nt > 2) op[tid + 256] = elu1(a2);
    if (nt > 3) op[tid + 384] = elu1(a3);
}

// ---------------- host side ----------------
struct LayerDims { int fin, hid, fout; };
static const LayerDims g_dims[6] = {
    {256, 128, 128}, {128, 256, 256}, {256, 512, 384},
    {384, 512, 256}, {256, 256, 128}, {128, 128, 256}
};

extern "C" void kernel_launch(void* const* d_in, const int* in_sizes, int n_in,
                              void* d_out, int out_size) {
    const float* x   = (const float*)d_in[0];
    const float* adj = (const float*)d_in[1];

    float *p_h, *p_hcat, *p_s1, *p_s2, *p_att, *p_ho, *p_o1, *p_o2, *p_x0, *p_x1;
    int *p_deg, *p_rowptr, *p_colidx;
    cudaGetSymbolAddress((void**)&p_deg, g_deg);
    cudaGetSymbolAddress((void**)&p_rowptr, g_rowptr);
    cudaGetSymbolAddress((void**)&p_colidx, g_colidx);
    cudaGetSymbolAddress((void**)&p_h, g_h);
    cudaGetSymbolAddress((void**)&p_hcat, g_hcat);
    cudaGetSymbolAddress((void**)&p_s1, g_s1);
    cudaGetSymbolAddress((void**)&p_s2, g_s2);
    cudaGetSymbolAddress((void**)&p_att, g_att);
    cudaGetSymbolAddress((void**)&p_ho, g_ho);
    cudaGetSymbolAddress((void**)&p_o1, g_o1);
    cudaGetSymbolAddress((void**)&p_o2, g_o2);
    cudaGetSymbolAddress((void**)&p_x0, g_xb0);
    cudaGetSymbolAddress((void**)&p_x1, g_xb1);

    // Build CSR of adjacency (deterministic, ascending column order)
    csr_count<<<NN / 8, 256>>>(adj, p_deg);
    csr_scan<<<1, 1024>>>(p_deg, p_rowptr);
    csr_fill<<<NN / 8, 256>>>(adj, p_rowptr, p_colidx);

    const float* xin = x;
    for (int l = 0; l < 6; l++) {
        int fin = g_dims[l].fin, hid = g_dims[l].hid, fout = g_dims[l].fout;
        const float* Wh = (const float*)d_in[2 + 4 * l];
        const float* ah = (const float*)d_in[3 + 4 * l];
        const float* Wo = (const float*)d_in[4 + 4 * l];
        const float* ao = (const float*)d_in[5 + 4 * l];

        // h[head] = x @ Wh[head]   (batched over heads)
        sgemm64<<<dim3(hid / 64, NN / 64, NH), dim3(16, 16)>>>(
            xin, Wh, p_h, NN, hid, fin,
            0L, (long)fin * hid, (long)NN * hid);

        // s1/s2
        int totalHN = NH * NN;
        dot_s<<<(totalHN * 32 + 255) / 256, 256>>>(p_h, ah, p_s1, p_s2, hid, totalHN);

        // per-head masked softmax over neighbor lists
        att_softmax<<<(totalHN * 32 + 255) / 256, 256>>>(p_rowptr, p_colidx, p_s1, p_s2, p_att, totalHN);

        // hcat = elu(att @ h), concatenated over heads
        spmm_elu<<<dim3(NN, NH), 128>>>(p_rowptr, p_colidx, p_att, p_h, p_hcat, hid, NH * hid);

        // ho = hcat @ Wo
        sgemm64<<<dim3(fout / 64, NN / 64, 1), dim3(16, 16)>>>(
            p_hcat, Wo, p_ho, NN, fout, NH * hid, 0L, 0L, 0L);

        // o1/o2 dot products (single "head")
        dot_s<<<(NN * 32 + 255) / 256, 256>>>(p_ho, ao, p_o1, p_o2, fout, NN);

        // output attention softmax
        att_softmax<<<(NN * 32 + 255) / 256, 256>>>(p_rowptr, p_colidx, p_o1, p_o2, p_att, NN);

        // next x = elu(ato @ ho)
        float* xout = (l == 5) ? (float*)d_out : ((l & 1) ? p_x1 : p_x0);
        spmm_elu<<<dim3(NN, 1), 128>>>(p_rowptr, p_colidx, p_att, p_ho, xout, fout, fout);

        xin = xout;
    }
    (void)in_sizes; (void)n_in; (void)out_size;
}

// round 2
// speedup vs baseline: 1.4027x; 1.4027x over previous
#include <cuda_runtime.h>
#include <cuda_bf16.h>
#include <math.h>

#define NN 2048          // nodes
#define NH 8             // heads
#define ALPHA 0.2f
#define NNZ_CAP (2048*128)
#define HID_MAX 512
#define KSPLIT 8

// ---------------- scratch (static device allocations) ----------------
__device__ int   g_deg[NN];
__device__ int   g_rowptr[NN + 1];
__device__ int   g_colidx[NNZ_CAP];
__device__ float g_h[NH * NN * HID_MAX];        // per-head projected features
__device__ float g_hcat[NN * NH * HID_MAX];     // concat heads
__device__ float g_s1[NH * NN];
__device__ float g_s2[NH * NN];
__device__ float g_att[(size_t)NH * NNZ_CAP];
__device__ float g_ho[NN * HID_MAX];
__device__ float g_o1[NN];
__device__ float g_o2[NN];
__device__ float g_xb0[NN * HID_MAX];
__device__ float g_xb1[NN * HID_MAX];
__device__ float g_part[KSPLIT * NN * 384];     // split-K partials for Wo gemm

// ---------------- CSR build ----------------
__global__ void csr_count(const float* __restrict__ adj, int* __restrict__ deg) {
    int row = blockIdx.x * (blockDim.x >> 5) + (threadIdx.x >> 5);
    if (row >= NN) return;
    int lane = threadIdx.x & 31;
    const float* r = adj + (size_t)row * NN;
    int cnt = 0;
    for (int c0 = 0; c0 < NN; c0 += 32) {
        float v = r[c0 + lane];
        unsigned m = __ballot_sync(0xffffffffu, v > 0.f);
        cnt += __popc(m);
    }
    if (lane == 0) deg[row] = cnt;
}

__global__ void csr_scan(const int* __restrict__ deg, int* __restrict__ rowptr) {
    __shared__ int s[1024];
    int t = threadIdx.x;                  // 1024 threads
    int d0 = deg[2 * t], d1 = deg[2 * t + 1];
    s[t] = d0 + d1;
    __syncthreads();
    for (int off = 1; off < 1024; off <<= 1) {
        int v = s[t];
        int add = (t >= off) ? s[t - off] : 0;
        __syncthreads();
        s[t] = v + add;
        __syncthreads();
    }
    int excl = (t > 0) ? s[t - 1] : 0;    // exclusive sum of pairs
    rowptr[2 * t]     = excl;
    rowptr[2 * t + 1] = excl + d0;
    if (t == 1023) rowptr[NN] = s[1023];
}

__global__ void csr_fill(const float* __restrict__ adj, const int* __restrict__ rowptr,
                         int* __restrict__ colidx) {
    int row = blockIdx.x * (blockDim.x >> 5) + (threadIdx.x >> 5);
    if (row >= NN) return;
    int lane = threadIdx.x & 31;
    const float* r = adj + (size_t)row * NN;
    int pos = rowptr[row];
    for (int c0 = 0; c0 < NN; c0 += 32) {
        float v = r[c0 + lane];
        unsigned m = __ballot_sync(0xffffffffu, v > 0.f);
        if (v > 0.f) {
            int off = __popc(m & ((1u << lane) - 1u));
            colidx[pos + off] = c0 + lane;
        }
        pos += __popc(m);
    }
}

// ---------------- 128x128x8 double-buffered fp32 GEMM ----------------
// C(M x N) = A(M x lda, using Kc columns) * B(Kc x N). Per-z strides allow
// batching over heads (Wh) or split-K chunks (Wo). Requires M%128==0,
// N%128==0, Kc%8==0, lda%4==0.
__global__ void __launch_bounds__(256, 2) sgemm128(
    const float* __restrict__ A, const float* __restrict__ B, float* __restrict__ C,
    int M, int N, int Kc, int lda,
    long sAz, long sBz, long sCz)
{
    A += (long)blockIdx.z * sAz;
    B += (long)blockIdx.z * sBz;
    C += (long)blockIdx.z * sCz;

    __shared__ float As[2][8][132];   // padded: conflict-free transposed stores
    __shared__ float Bs[2][8][128];

    int tid = threadIdx.x;
    int rowBase = blockIdx.y * 128;
    int colBase = blockIdx.x * 128;

    // A loader: thread -> (row = tid/2, kcol = (tid%2)*4), float4 along K
    int aRow = tid >> 1;
    int aCol = (tid & 1) << 2;
    // B loader: thread -> (krow = tid/32, col = (tid%32)*4)
    int bRow = tid >> 5;
    int bCol = (tid & 31) << 2;

    const float* Aptr = A + (size_t)(rowBase + aRow) * lda + aCol;
    const float* Bptr = B + (size_t)bRow * N + colBase + bCol;

    int tx = tid & 15, ty = tid >> 4;

    float acc[8][8];
#pragma unroll
    for (int i = 0; i < 8; i++)
#pragma unroll
        for (int j = 0; j < 8; j++) acc[i][j] = 0.f;

    // preload tile 0
    float4 ra = *(const float4*)Aptr;
    float4 rb = *(const float4*)Bptr;
    As[0][aCol + 0][aRow] = ra.x;
    As[0][aCol + 1][aRow] = ra.y;
    As[0][aCol + 2][aRow] = ra.z;
    As[0][aCol + 3][aRow] = ra.w;
    *(float4*)&Bs[0][bRow][bCol] = rb;
    __syncthreads();

    int nT = Kc >> 3;
    int buf = 0;
    for (int t = 0; t < nT; t++) {
        if (t + 1 < nT) {
            ra = *(const float4*)(Aptr + (t + 1) * 8);
            rb = *(const float4*)(Bptr + (size_t)(t + 1) * 8 * N);
        }
#pragma unroll
        for (int k = 0; k < 8; k++) {
            float4 a0 = *(const float4*)&As[buf][k][ty << 2];
            float4 a1 = *(const float4*)&As[buf][k][(ty << 2) + 64];
            float4 b0 = *(const float4*)&Bs[buf][k][tx << 2];
            float4 b1 = *(const float4*)&Bs[buf][k][(tx << 2) + 64];
            float av[8] = {a0.x, a0.y, a0.z, a0.w, a1.x, a1.y, a1.z, a1.w};
            float bv[8] = {b0.x, b0.y, b0.z, b0.w, b1.x, b1.y, b1.z, b1.w};
#pragma unroll
            for (int i = 0; i < 8; i++)
#pragma unroll
                for (int j = 0; j < 8; j++)
                    acc[i][j] += av[i] * bv[j];
        }
        if (t + 1 < nT) {
            int nb = buf ^ 1;
            As[nb][aCol + 0][aRow] = ra.x;
            As[nb][aCol + 1][aRow] = ra.y;
            As[nb][aCol + 2][aRow] = ra.z;
            As[nb][aCol + 3][aRow] = ra.w;
            *(float4*)&Bs[nb][bRow][bCol] = rb;
            __syncthreads();
            buf = nb;
        }
    }

#pragma unroll
    for (int i = 0; i < 4; i++) {
        float* c0 = C + (size_t)(rowBase + (ty << 2) + i) * N + colBase;
        *(float4*)&c0[tx << 2]        = make_float4(acc[i][0], acc[i][1], acc[i][2], acc[i][3]);
        *(float4*)&c0[(tx << 2) + 64] = make_float4(acc[i][4], acc[i][5], acc[i][6], acc[i][7]);
        float* c1 = C + (size_t)(rowBase + (ty << 2) + 64 + i) * N + colBase;
        *(float4*)&c1[tx << 2]        = make_float4(acc[i + 4][0], acc[i + 4][1], acc[i + 4][2], acc[i + 4][3]);
        *(float4*)&c1[(tx << 2) + 64] = make_float4(acc[i + 4][4], acc[i + 4][5], acc[i + 4][6], acc[i + 4][7]);
    }
}

// Deterministic split-K reduction: out[i] = sum_s part[s*MN + i]
__global__ void reduce_split(const float* __restrict__ part, float* __restrict__ out, int MN) {
    int i = (blockIdx.x * blockDim.x + threadIdx.x) << 2;
    if (i >= MN) return;
    float4 s = make_float4(0.f, 0.f, 0.f, 0.f);
#pragma unroll
    for (int p = 0; p < KSPLIT; p++) {
        float4 v = *(const float4*)&part[(size_t)p * MN + i];
        s.x += v.x; s.y += v.y; s.z += v.z; s.w += v.w;
    }
    *(float4*)&out[i] = s;
}

// ---------------- s1/s2 dot products (warp per (head,node)) ----------------
__global__ void dot_s(const float* __restrict__ h, const float* __restrict__ a,
                      float* __restrict__ s1, float* __restrict__ s2, int hid, int total) {
    int w = (blockIdx.x * blockDim.x + threadIdx.x) >> 5;
    if (w >= total) return;
    int lane = threadIdx.x & 31;
    int head = w / NN;
    const float* hp = h + (size_t)w * hid;
    const float* a1 = a + (size_t)head * 2 * hid;
    const float* a2 = a1 + hid;
    float v1 = 0.f, v2 = 0.f;
    for (int d = lane; d < hid; d += 32) {
        float x = hp[d];
        v1 += x * a1[d];
        v2 += x * a2[d];
    }
#pragma unroll
    for (int o = 16; o; o >>= 1) {
        v1 += __shfl_xor_sync(0xffffffffu, v1, o);
        v2 += __shfl_xor_sync(0xffffffffu, v2, o);
    }
    if (lane == 0) { s1[w] = v1; s2[w] = v2; }
}

// ---------------- masked softmax over neighbor lists (warp per (head,row)) ----------------
__global__ void att_softmax(const int* __restrict__ rowptr, const int* __restrict__ colidx,
                            const float* __restrict__ s1, const float* __restrict__ s2,
                            float* __restrict__ att, int total) {
    int w = (blockIdx.x * blockDim.x + threadIdx.x) >> 5;
    if (w >= total) return;
    int lane = threadIdx.x & 31;
    int head = w / NN;
    int i = w - head * NN;
    int b = rowptr[i], e = rowptr[i + 1];
    const float* s2h = s2 + (size_t)head * NN;
    float si = s1[w];
    float m = -1e30f;
    for (int k = b + lane; k < e; k += 32) {
        float v = si + s2h[colidx[k]];
        v = v > 0.f ? v : ALPHA * v;
        m = fmaxf(m, v);
    }
#pragma unroll
    for (int o = 16; o; o >>= 1) m = fmaxf(m, __shfl_xor_sync(0xffffffffu, m, o));
    float sum = 0.f;
    float* ah = att + (size_t)head * NNZ_CAP;
    for (int k = b + lane; k < e; k += 32) {
        float v = si + s2h[colidx[k]];
        v = v > 0.f ? v : ALPHA * v;
        float ex = expf(v - m);
        ah[k] = ex;
        sum += ex;
    }
#pragma unroll
    for (int o = 16; o; o >>= 1) sum += __shfl_xor_sync(0xffffffffu, sum, o);
    float inv = 1.f / sum;
    for (int k = b + lane; k < e; k += 32) ah[k] *= inv;
}

// ---------------- sparse att @ h with ELU epilogue (block per (row,head)) ----------------
__device__ __forceinline__ float elu1(float x) { return x > 0.f ? x : expm1f(x); }

__global__ void spmm_elu(const int* __restrict__ rowptr, const int* __restrict__ colidx,
                         const float* __restrict__ att, const float* __restrict__ h,
                         float* __restrict__ out, int hid, int out_stride) {
    int i = blockIdx.x, head = blockIdx.y;
    int tid = threadIdx.x;                    // 128
    int b = rowptr[i], e = rowptr[i + 1];
    const float* hb = h + (size_t)head * NN * hid;
    const float* av = att + (size_t)head * NNZ_CAP;
    int nt = hid >> 7;                        // hid in {128,256,384,512}
    float a0 = 0.f, a1 = 0.f, a2 = 0.f, a3 = 0.f;
#pragma unroll 4
    for (int k = b; k < e; k++) {
        int j = colidx[k];
        float a = __ldg(&av[k]);
        const float* hr = hb + (size_t)j * hid;
        a0 += a * hr[tid];
        if (nt > 1) a1 += a * hr[tid + 128];
        if (nt > 2) a2 += a * hr[tid + 256];
        if (nt > 3) a3 += a * hr[tid + 384];
    }
    float* op = out + (size_t)i * out_stride + (size_t)head * hid;
    op[tid] = elu1(a0);
    if (nt > 1) op[tid + 128] = elu1(a1);
    if (nt > 2) op[tid + 256] = elu1(a2);
    if (nt > 3) op[tid + 384] = elu1(a3);
}

// ---------------- host side ----------------
struct LayerDims { int fin, hid, fout; };
static const LayerDims g_dims[6] = {
    {256, 128, 128}, {128, 256, 256}, {256, 512, 384},
    {384, 512, 256}, {256, 256, 128}, {128, 128, 256}
};

extern "C" void kernel_launch(void* const* d_in, const int* in_sizes, int n_in,
                              void* d_out, int out_size) {
    const float* x   = (const float*)d_in[0];
    const float* adj = (const float*)d_in[1];

    float *p_h, *p_hcat, *p_s1, *p_s2, *p_att, *p_ho, *p_o1, *p_o2, *p_x0, *p_x1, *p_part;
    int *p_deg, *p_rowptr, *p_colidx;
    cudaGetSymbolAddress((void**)&p_deg, g_deg);
    cudaGetSymbolAddress((void**)&p_rowptr, g_rowptr);
    cudaGetSymbolAddress((void**)&p_colidx, g_colidx);
    cudaGetSymbolAddress((void**)&p_h, g_h);
    cudaGetSymbolAddress((void**)&p_hcat, g_hcat);
    cudaGetSymbolAddress((void**)&p_s1, g_s1);
    cudaGetSymbolAddress((void**)&p_s2, g_s2);
    cudaGetSymbolAddress((void**)&p_att, g_att);
    cudaGetSymbolAddress((void**)&p_ho, g_ho);
    cudaGetSymbolAddress((void**)&p_o1, g_o1);
    cudaGetSymbolAddress((void**)&p_o2, g_o2);
    cudaGetSymbolAddress((void**)&p_x0, g_xb0);
    cudaGetSymbolAddress((void**)&p_x1, g_xb1);
    cudaGetSymbolAddress((void**)&p_part, g_part);

    // Build CSR of adjacency (deterministic, ascending column order)
    csr_count<<<NN / 8, 256>>>(adj, p_deg);
    csr_scan<<<1, 1024>>>(p_deg, p_rowptr);
    csr_fill<<<NN / 8, 256>>>(adj, p_rowptr, p_colidx);

    const float* xin = x;
    for (int l = 0; l < 6; l++) {
        int fin = g_dims[l].fin, hid = g_dims[l].hid, fout = g_dims[l].fout;
        const float* Wh = (const float*)d_in[2 + 4 * l];
        const float* ah = (const float*)d_in[3 + 4 * l];
        const float* Wo = (const float*)d_in[4 + 4 * l];
        const float* ao = (const float*)d_in[5 + 4 * l];

        // h[head] = x @ Wh[head]   (batched over heads, z = head)
        sgemm128<<<dim3(hid / 128, NN / 128, NH), 256>>>(
            xin, Wh, p_h, NN, hid, fin, fin,
            0L, (long)fin * hid, (long)NN * hid);

        // s1/s2
        int totalHN = NH * NN;
        dot_s<<<(totalHN * 32 + 255) / 256, 256>>>(p_h, ah, p_s1, p_s2, hid, totalHN);

        // per-head masked softmax over neighbor lists
        att_softmax<<<(totalHN * 32 + 255) / 256, 256>>>(p_rowptr, p_colidx, p_s1, p_s2, p_att, totalHN);

        // hcat = elu(att @ h), concatenated over heads
        spmm_elu<<<dim3(NN, NH), 128>>>(p_rowptr, p_colidx, p_att, p_h, p_hcat, hid, NH * hid);

        // ho = hcat @ Wo via split-K (z = K chunk), then deterministic reduce
        int Ktot = NH * hid;
        int Kc = Ktot / KSPLIT;
        sgemm128<<<dim3(fout / 128, NN / 128, KSPLIT), 256>>>(
            p_hcat, Wo, p_part, NN, fout, Kc, Ktot,
            (long)Kc, (long)Kc * fout, (long)NN * fout);
        reduce_split<<<(NN * fout / 4 + 255) / 256, 256>>>(p_part, p_ho, NN * fout);

        // o1/o2 dot products (single "head")
        dot_s<<<(NN * 32 + 255) / 256, 256>>>(p_ho, ao, p_o1, p_o2, fout, NN);

        // output attention softmax
        att_softmax<<<(NN * 32 + 255) / 256, 256>>>(p_rowptr, p_colidx, p_o1, p_o2, p_att, NN);

        // next x = elu(ato @ ho)
        float* xout = (l == 5) ? (float*)d_out : ((l & 1) ? p_x1 : p_x0);
        spmm_elu<<<dim3(NN, 1), 128>>>(p_rowptr, p_colidx, p_att, p_ho, xout, fout, fout);

        xin = xout;
    }
    (void)in_sizes; (void)n_in; (void)out_size;
}

// round 4
// speedup vs baseline: 1.7704x; 1.2622x over previous
#include <cuda_runtime.h>
#include <cuda_bf16.h>
#include <math.h>
#include <stdint.h>

#define NN 2048          // nodes
#define NH 8             // heads
#define ALPHA 0.2f
#define NNZ_CAP (2048*128)
#define HID_MAX 512
#define KSPLIT 8

// ---------------- scratch (static device allocations) ----------------
__device__ int   g_deg[NN];
__device__ int   g_rowptr[NN + 1];
__device__ int   g_colidx[NNZ_CAP];
__device__ float g_h[NH * NN * HID_MAX];        // per-head projected features
__device__ float g_hcat[NN * NH * HID_MAX];     // concat heads
__device__ float g_s1[NH * NN];
__device__ float g_s2[NH * NN];
__device__ float g_att[(size_t)NH * NNZ_CAP];
__device__ float g_ho[NN * HID_MAX];
__device__ float g_o1[NN];
__device__ float g_o2[NN];
__device__ float g_xb0[NN * HID_MAX];
__device__ float g_xb1[NN * HID_MAX];
__device__ float g_part[KSPLIT * NN * 384];     // split-K partials for Wo gemm
// bf16 hi/lo operand buffers
__device__ __nv_bfloat16 g_a1[NN * 4096];
__device__ __nv_bfloat16 g_a2[NN * 4096];
__device__ __nv_bfloat16 g_b1[1 << 21];
__device__ __nv_bfloat16 g_b2[1 << 21];

// ---------------- bf16 hi/lo elementwise split ----------------
__global__ void split_bf(const float* __restrict__ in, __nv_bfloat16* __restrict__ o1,
                         __nv_bfloat16* __restrict__ o2, long n4) {
    long i = (long)blockIdx.x * blockDim.x + threadIdx.x;
    if (i >= n4) return;
    float4 v = ((const float4*)in)[i];
    __nv_bfloat16 h0 = __float2bfloat16_rn(v.x), h1 = __float2bfloat16_rn(v.y);
    __nv_bfloat16 h2 = __float2bfloat16_rn(v.z), h3 = __float2bfloat16_rn(v.w);
    __nv_bfloat16 l0 = __float2bfloat16_rn(v.x - __bfloat162float(h0));
    __nv_bfloat16 l1 = __float2bfloat16_rn(v.y - __bfloat162float(h1));
    __nv_bfloat16 l2 = __float2bfloat16_rn(v.z - __bfloat162float(h2));
    __nv_bfloat16 l3 = __float2bfloat16_rn(v.w - __bfloat162float(h3));
    ushort4 uh, ul;
    uh.x = *(unsigned short*)&h0; uh.y = *(unsigned short*)&h1;
    uh.z = *(unsigned short*)&h2; uh.w = *(unsigned short*)&h3;
    ul.x = *(unsigned short*)&l0; ul.y = *(unsigned short*)&l1;
    ul.z = *(unsigned short*)&l2; ul.w = *(unsigned short*)&l3;
    ((ushort4*)o1)[i] = uh;
    ((ushort4*)o2)[i] = ul;
}

// ---------------- HMMA bf16x2 GEMM ----------------
// C(tile 128x128) = A * B, A [z][M][K] bf16 hi/lo (lda, sAz elems),
// B [z][K][N] bf16 hi/lo (ldb, sBz), C fp32 (ldc, sCz). Kc % 32 == 0.
// 3-product decomposition: C = A1*B1 + A1*B2 + A2*B1.

#define A_ST 40          // smem row stride in bf16 (128 rows x 32 cols)
#define B_ST 136         // smem row stride in bf16 (32 rows x 128 cols)
#define A_BYTES (128 * A_ST * 2)        // 10240
#define B_BYTES (32 * B_ST * 2)         // 8704
#define BUF_BYTES (2 * A_BYTES + 2 * B_BYTES)   // 37888
#define GSMEM_BYTES (2 * BUF_BYTES)             // 75776

__device__ __forceinline__ uint32_t smem_u32(const void* p) {
    uint32_t a;
    asm("{ .reg .u64 t; cvta.to.shared.u64 t, %1; cvt.u32.u64 %0, t; }" : "=r"(a) : "l"(p));
    return a;
}

#define LDMX4(r0, r1, r2, r3, addr) \
    asm volatile("ldmatrix.sync.aligned.m8n8.x4.shared.b16 {%0,%1,%2,%3}, [%4];" \
                 : "=r"(r0), "=r"(r1), "=r"(r2), "=r"(r3) : "r"(addr))
#define LDMX2T(r0, r1, addr) \
    asm volatile("ldmatrix.sync.aligned.m8n8.x2.trans.shared.b16 {%0,%1}, [%2];" \
                 : "=r"(r0), "=r"(r1) : "r"(addr))
#define MMA16816(acc, a, b) \
    asm volatile("mma.sync.aligned.m16n8k16.row.col.f32.bf16.bf16.f32 " \
                 "{%0,%1,%2,%3}, {%4,%5,%6,%7}, {%8,%9}, {%0,%1,%2,%3};" \
                 : "+f"((acc)[0]), "+f"((acc)[1]), "+f"((acc)[2]), "+f"((acc)[3]) \
                 : "r"((a)[0]), "r"((a)[1]), "r"((a)[2]), "r"((a)[3]), \
                   "r"((b)[0]), "r"((b)[1]))

__global__ void __launch_bounds__(256, 1) gemm_mma(
    const __nv_bfloat16* __restrict__ A1, const __nv_bfloat16* __restrict__ A2,
    long lda, long sAz,
    const __nv_bfloat16* __restrict__ B1, const __nv_bfloat16* __restrict__ B2,
    long ldb, long sBz,
    float* __restrict__ C, long ldc, long sCz, int Kc)
{
    extern __shared__ char sm[];
    int tid = threadIdx.x;
    int wid = tid >> 5, lane = tid & 31;
    int mBase = blockIdx.y * 128;
    int nBase = blockIdx.x * 128;
    int z = blockIdx.z;

    const __nv_bfloat16* a1 = A1 + (long)z * sAz + (size_t)mBase * lda;
    const __nv_bfloat16* a2 = A2 + (long)z * sAz + (size_t)mBase * lda;
    const __nv_bfloat16* b1 = B1 + (long)z * sBz + nBase;
    const __nv_bfloat16* b2 = B2 + (long)z * sBz + nBase;
    float* c = C + (long)z * sCz;

    // loader indices
    int acRow0 = tid >> 1;              // chunk c = 0*256+tid ... actually c>>2 layout below
    (void)acRow0;

    float acc[4][4][4];
#pragma unroll
    for (int i = 0; i < 4; i++)
#pragma unroll
        for (int j = 0; j < 4; j++)
#pragma unroll
            for (int r = 0; r < 4; r++) acc[i][j][r] = 0.f;

    int mW = (wid >> 2) * 64;
    int nW = (wid & 3) * 32;

    uint32_t sb = smem_u32(sm);

    uint4 ra1[2], ra2[2], rb1[2], rb2[2];

    // ---- prefetch tile 0 into regs ----
#pragma unroll
    for (int i = 0; i < 2; i++) {
        int c = i * 256 + tid;
        int r = c >> 2, ch = c & 3;                 // A: 128 rows x 4 chunks(16B)
        ra1[i] = *(const uint4*)((const char*)a1 + (size_t)r * lda * 2 + ch * 16);
        ra2[i] = *(const uint4*)((const char*)a2 + (size_t)r * lda * 2 + ch * 16);
        int rB = c >> 4, chB = c & 15;              // B: 32 rows x 16 chunks(16B)
        rb1[i] = *(const uint4*)((const char*)b1 + (size_t)rB * ldb * 2 + chB * 16);
        rb2[i] = *(const uint4*)((const char*)b2 + (size_t)rB * ldb * 2 + chB * 16);
    }
    // store tile 0 -> buffer 0
#pragma unroll
    for (int i = 0; i < 2; i++) {
        int c = i * 256 + tid;
        int r = c >> 2, ch = c & 3;
        *(uint4*)(sm + r * (A_ST * 2) + ch * 16) = ra1[i];
        *(uint4*)(sm + A_BYTES + r * (A_ST * 2) + ch * 16) = ra2[i];
        int rB = c >> 4, chB = c & 15;
        *(uint4*)(sm + 2 * A_BYTES + rB * (B_ST * 2) + chB * 16) = rb1[i];
        *(uint4*)(sm + 2 * A_BYTES + B_BYTES + rB * (B_ST * 2) + chB * 16) = rb2[i];
    }
    __syncthreads();

    int nT = Kc >> 5;
    for (int t = 0; t < nT; t++) {
        if (t + 1 < nT) {
#pragma unroll
            for (int i = 0; i < 2; i++) {
                int cch = i * 256 + tid;
                int r = cch >> 2, ch = cch & 3;
                const char* pa = (const char*)a1 + (size_t)r * lda * 2 + (t + 1) * 64 + ch * 16;
                const char* pa2 = (const char*)a2 + (size_t)r * lda * 2 + (t + 1) * 64 + ch * 16;
                ra1[i] = *(const uint4*)pa;
                ra2[i] = *(const uint4*)pa2;
                int rB = cch >> 4, chB = cch & 15;
                rb1[i] = *(const uint4*)((const char*)b1 + (size_t)((t + 1) * 32 + rB) * ldb * 2 + chB * 16);
                rb2[i] = *(const uint4*)((const char*)b2 + (size_t)((t + 1) * 32 + rB) * ldb * 2 + chB * 16);
            }
        }
        uint32_t bufb = sb + (uint32_t)(t & 1) * BUF_BYTES;
        uint32_t sA1 = bufb;
        uint32_t sA2 = bufb + A_BYTES;
        uint32_t sB1 = bufb + 2 * A_BYTES;
        uint32_t sB2 = bufb + 2 * A_BYTES + B_BYTES;

#pragma unroll
        for (int kk = 0; kk < 32; kk += 16) {
            uint32_t af[2][4][4];
            uint32_t bfr[2][4][2];
#pragma unroll
            for (int mt = 0; mt < 4; mt++) {
                uint32_t off = (uint32_t)((mW + mt * 16 + (lane & 15)) * (A_ST * 2)
                                          + (kk + ((lane >> 4) << 3)) * 2);
                LDMX4(af[0][mt][0], af[0][mt][1], af[0][mt][2], af[0][mt][3], sA1 + off);
                LDMX4(af[1][mt][0], af[1][mt][1], af[1][mt][2], af[1][mt][3], sA2 + off);
            }
#pragma unroll
            for (int nt = 0; nt < 4; nt++) {
                uint32_t off = (uint32_t)((kk + (lane & 15)) * (B_ST * 2)
                                          + (nW + nt * 8) * 2);
                LDMX2T(bfr[0][nt][0], bfr[0][nt][1], sB1 + off);
                LDMX2T(bfr[1][nt][0], bfr[1][nt][1], sB2 + off);
            }
#pragma unroll
            for (int mt = 0; mt < 4; mt++)
#pragma unroll
                for (int nt = 0; nt < 4; nt++) {
                    MMA16816(acc[mt][nt], af[0][mt], bfr[0][nt]);
                    MMA16816(acc[mt][nt], af[0][mt], bfr[1][nt]);
                    MMA16816(acc[mt][nt], af[1][mt], bfr[0][nt]);
                }
        }
        if (t + 1 < nT) {
            char* nb = sm + ((t + 1) & 1) * BUF_BYTES;
#pragma unroll
            for (int i = 0; i < 2; i++) {
                int cch = i * 256 + tid;
                int r = cch >> 2, ch = cch & 3;
                *(uint4*)(nb + r * (A_ST * 2) + ch * 16) = ra1[i];
                *(uint4*)(nb + A_BYTES + r * (A_ST * 2) + ch * 16) = ra2[i];
                int rB = cch >> 4, chB = cch & 15;
                *(uint4*)(nb + 2 * A_BYTES + rB * (B_ST * 2) + chB * 16) = rb1[i];
                *(uint4*)(nb + 2 * A_BYTES + B_BYTES + rB * (B_ST * 2) + chB * 16) = rb2[i];
            }
            __syncthreads();
        }
    }

    // epilogue: m16n8 fragment mapping
#pragma unroll
    for (int mt = 0; mt < 4; mt++) {
        int row0 = mBase + mW + mt * 16 + (lane >> 2);
#pragma unroll
        for (int nt = 0; nt < 4; nt++) {
            int col = nBase + nW + nt * 8 + (lane & 3) * 2;
            float* cr = c + (size_t)row0 * ldc + col;
            *(float2*)cr = make_float2(acc[mt][nt][0], acc[mt][nt][1]);
            *(float2*)(cr + 8 * ldc) = make_float2(acc[mt][nt][2], acc[mt][nt][3]);
        }
    }
}

// ---------------- CSR build ----------------
__global__ void csr_count(const float* __restrict__ adj, int* __restrict__ deg) {
    int row = blockIdx.x * (blockDim.x >> 5) + (threadIdx.x >> 5);
    if (row >= NN) return;
    int lane = threadIdx.x & 31;
    const float* r = adj + (size_t)row * NN;
    int cnt = 0;
    for (int c0 = 0; c0 < NN; c0 += 32) {
        float v = r[c0 + lane];
        unsigned m = __ballot_sync(0xffffffffu, v > 0.f);
        cnt += __popc(m);
    }
    if (lane == 0) deg[row] = cnt;
}

__global__ void csr_scan(const int* __restrict__ deg, int* __restrict__ rowptr) {
    __shared__ int s[1024];
    int t = threadIdx.x;
    int d0 = deg[2 * t], d1 = deg[2 * t + 1];
    s[t] = d0 + d1;
    __syncthreads();
    for (int off = 1; off < 1024; off <<= 1) {
        int v = s[t];
        int add = (t >= off) ? s[t - off] : 0;
        __syncthreads();
        s[t] = v + add;
        __syncthreads();
    }
    int excl = (t > 0) ? s[t - 1] : 0;
    rowptr[2 * t]     = excl;
    rowptr[2 * t + 1] = excl + d0;
    if (t == 1023) rowptr[NN] = s[1023];
}

__global__ void csr_fill(const float* __restrict__ adj, const int* __restrict__ rowptr,
                         int* __restrict__ colidx) {
    int row = blockIdx.x * (blockDim.x >> 5) + (threadIdx.x >> 5);
    if (row >= NN) return;
    int lane = threadIdx.x & 31;
    const float* r = adj + (size_t)row * NN;
    int pos = rowptr[row];
    for (int c0 = 0; c0 < NN; c0 += 32) {
        float v = r[c0 + lane];
        unsigned m = __ballot_sync(0xffffffffu, v > 0.f);
        if (v > 0.f) {
            int off = __popc(m & ((1u << lane) - 1u));
            colidx[pos + off] = c0 + lane;
        }
        pos += __popc(m);
    }
}

// Deterministic split-K reduction
__global__ void reduce_split(const float* __restrict__ part, float* __restrict__ out, int MN) {
    int i = (blockIdx.x * blockDim.x + threadIdx.x) << 2;
    if (i >= MN) return;
    float4 s = make_float4(0.f, 0.f, 0.f, 0.f);
#pragma unroll
    for (int p = 0; p < KSPLIT; p++) {
        float4 v = *(const float4*)&part[(size_t)p * MN + i];
        s.x += v.x; s.y += v.y; s.z += v.z; s.w += v.w;
    }
    *(float4*)&out[i] = s;
}

// ---------------- s1/s2 dot products ----------------
__global__ void dot_s(const float* __restrict__ h, const float* __restrict__ a,
                      float* __restrict__ s1, float* __restrict__ s2, int hid, int total) {
    int w = (blockIdx.x * blockDim.x + threadIdx.x) >> 5;
    if (w >= total) return;
    int lane = threadIdx.x & 31;
    int head = w / NN;
    const float* hp = h + (size_t)w * hid;
    const float* a1 = a + (size_t)head * 2 * hid;
    const float* a2 = a1 + hid;
    float v1 = 0.f, v2 = 0.f;
    for (int d = lane; d < hid; d += 32) {
        float x = hp[d];
        v1 += x * a1[d];
        v2 += x * a2[d];
    }
#pragma unroll
    for (int o = 16; o; o >>= 1) {
        v1 += __shfl_xor_sync(0xffffffffu, v1, o);
        v2 += __shfl_xor_sync(0xffffffffu, v2, o);
    }
    if (lane == 0) { s1[w] = v1; s2[w] = v2; }
}

// ---------------- masked softmax over neighbor lists ----------------
__global__ void att_softmax(const int* __restrict__ rowptr, const int* __restrict__ colidx,
                            const float* __restrict__ s1, const float* __restrict__ s2,
                            float* __restrict__ att, int total) {
    int w = (blockIdx.x * blockDim.x + threadIdx.x) >> 5;
    if (w >= total) return;
    int lane = threadIdx.x & 31;
    int head = w / NN;
    int i = w - head * NN;
    int b = rowptr[i], e = rowptr[i + 1];
    const float* s2h = s2 + (size_t)head * NN;
    float si = s1[w];
    float m = -1e30f;
    for (int k = b + lane; k < e; k += 32) {
        float v = si + s2h[colidx[k]];
        v = v > 0.f ? v : ALPHA * v;
        m = fmaxf(m, v);
    }
#pragma unroll
    for (int o = 16; o; o >>= 1) m = fmaxf(m, __shfl_xor_sync(0xffffffffu, m, o));
    float sum = 0.f;
    float* ah = att + (size_t)head * NNZ_CAP;
    for (int k = b + lane; k < e; k += 32) {
        float v = si + s2h[colidx[k]];
        v = v > 0.f ? v : ALPHA * v;
        float ex = expf(v - m);
        ah[k] = ex;
        sum += ex;
    }
#pragma unroll
    for (int o = 16; o; o >>= 1) sum += __shfl_xor_sync(0xffffffffu, sum, o);
    float inv = 1.f / sum;
    for (int k = b + lane; k < e; k += 32) ah[k] *= inv;
}

// ---------------- sparse att @ h with ELU epilogue ----------------
__device__ __forceinline__ float elu1(float x) { return x > 0.f ? x : expm1f(x); }

__global__ void spmm_elu(const int* __restrict__ rowptr, const int* __restrict__ colidx,
                         const float* __restrict__ att, const float* __restrict__ h,
                         float* __restrict__ out, int hid, int out_stride) {
    int i = blockIdx.x, head = blockIdx.y;
    int tid = threadIdx.x;                    // 128
    int b = rowptr[i], e = rowptr[i + 1];
    const float* hb = h + (size_t)head * NN * hid;
    const float* av = att + (size_t)head * NNZ_CAP;
    int nt = hid >> 7;
    float a0 = 0.f, a1 = 0.f, a2 = 0.f, a3 = 0.f;
#pragma unroll 4
    for (int k = b; k < e; k++) {
        int j = colidx[k];
        float a = __ldg(&av[k]);
        const float* hr = hb + (size_t)j * hid;
        a0 += a * hr[tid];
        if (nt > 1) a1 += a * hr[tid + 128];
        if (nt > 2) a2 += a * hr[tid + 256];
        if (nt > 3) a3 += a * hr[tid + 384];
    }
    float* op = out + (size_t)i * out_stride + (size_t)head * hid;
    op[tid] = elu1(a0);
    if (nt > 1) op[tid + 128] = elu1(a1);
    if (nt > 2) op[tid + 256] = elu1(a2);
    if (nt > 3) op[tid + 384] = elu1(a3);
}

// ---------------- host side ----------------
struct LayerDims { int fin, hid, fout; };
static const LayerDims g_dims[6] = {
    {256, 128, 128}, {128, 256, 256}, {256, 512, 384},
    {384, 512, 256}, {256, 256, 128}, {128, 128, 256}
};

extern "C" void kernel_launch(void* const* d_in, const int* in_sizes, int n_in,
                              void* d_out, int out_size) {
    const float* x   = (const float*)d_in[0];
    const float* adj = (const float*)d_in[1];

    float *p_h, *p_hcat, *p_s1, *p_s2, *p_att, *p_ho, *p_o1, *p_o2, *p_x0, *p_x1, *p_part;
    int *p_deg, *p_rowptr, *p_colidx;
    __nv_bfloat16 *p_a1, *p_a2, *p_b1, *p_b2;
    cudaGetSymbolAddress((void**)&p_deg, g_deg);
    cudaGetSymbolAddress((void**)&p_rowptr, g_rowptr);
    cudaGetSymbolAddress((void**)&p_colidx, g_colidx);
    cudaGetSymbolAddress((void**)&p_h, g_h);
    cudaGetSymbolAddress((void**)&p_hcat, g_hcat);
    cudaGetSymbolAddress((void**)&p_s1, g_s1);
    cudaGetSymbolAddress((void**)&p_s2, g_s2);
    cudaGetSymbolAddress((void**)&p_att, g_att);
    cudaGetSymbolAddress((void**)&p_ho, g_ho);
    cudaGetSymbolAddress((void**)&p_o1, g_o1);
    cudaGetSymbolAddress((void**)&p_o2, g_o2);
    cudaGetSymbolAddress((void**)&p_x0, g_xb0);
    cudaGetSymbolAddress((void**)&p_x1, g_xb1);
    cudaGetSymbolAddress((void**)&p_part, g_part);
    cudaGetSymbolAddress((void**)&p_a1, g_a1);
    cudaGetSymbolAddress((void**)&p_a2, g_a2);
    cudaGetSymbolAddress((void**)&p_b1, g_b1);
    cudaGetSymbolAddress((void**)&p_b2, g_b2);

    static int smem_set = 0;
    if (!smem_set) {
        cudaFuncSetAttribute(gemm_mma, cudaFuncAttributeMaxDynamicSharedMemorySize, GSMEM_BYTES);
        smem_set = 1;
    }

    // Build CSR of adjacency
    csr_count<<<NN / 8, 256>>>(adj, p_deg);
    csr_scan<<<1, 1024>>>(p_deg, p_rowptr);
    csr_fill<<<NN / 8, 256>>>(adj, p_rowptr, p_colidx);

    const float* xin = x;
    for (int l = 0; l < 6; l++) {
        int fin = g_dims[l].fin, hid = g_dims[l].hid, fout = g_dims[l].fout;
        const float* Wh = (const float*)d_in[2 + 4 * l];
        const float* ah = (const float*)d_in[3 + 4 * l];
        const float* Wo = (const float*)d_in[4 + 4 * l];
        const float* ao = (const float*)d_in[5 + 4 * l];

        // ---- head GEMM: h[head] = x @ Wh[head], bf16x2 HMMA ----
        split_bf<<<(NN * fin / 4 + 255) / 256, 256>>>(xin, p_a1, p_a2, NN * fin / 4);
        split_bf<<<((long)NH * fin * hid / 4 + 255) / 256, 256>>>(Wh, p_b1, p_b2, (long)NH * fin * hid / 4);
        gemm_mma<<<dim3(hid / 128, NN / 128, NH), 256, GSMEM_BYTES>>>(
            p_a1, p_a2, fin, 0L,
            p_b1, p_b2, hid, (long)fin * hid,
            p_h, hid, (long)NN * hid, fin);

        // s1/s2, softmax, head SpMM
        int totalHN = NH * NN;
        dot_s<<<(totalHN * 32 + 255) / 256, 256>>>(p_h, ah, p_s1, p_s2, hid, totalHN);
        att_softmax<<<(totalHN * 32 + 255) / 256, 256>>>(p_rowptr, p_colidx, p_s1, p_s2, p_att, totalHN);
        spmm_elu<<<dim3(NN, NH), 128>>>(p_rowptr, p_colidx, p_att, p_h, p_hcat, hid, NH * hid);

        // ---- output GEMM: ho = hcat @ Wo, bf16x2 HMMA split-K ----
        int Ktot = NH * hid;
        int Kc = Ktot / KSPLIT;
        split_bf<<<((long)NN * Ktot / 4 + 255) / 256, 256>>>(p_hcat, p_a1, p_a2, (long)NN * Ktot / 4);
        split_bf<<<((long)Ktot * fout / 4 + 255) / 256, 256>>>(Wo, p_b1, p_b2, (long)Ktot * fout / 4);
        gemm_mma<<<dim3(fout / 128, NN / 128, KSPLIT), 256, GSMEM_BYTES>>>(
            p_a1, p_a2, Ktot, (long)Kc,
            p_b1, p_b2, fout, (long)Kc * fout,
            p_part, fout, (long)NN * fout, Kc);
        reduce_split<<<(NN * fout / 4 + 255) / 256, 256>>>(p_part, p_ho, NN * fout);

        dot_s<<<(NN * 32 + 255) / 256, 256>>>(p_ho, ao, p_o1, p_o2, fout, NN);
        att_softmax<<<(NN * 32 + 255) / 256, 256>>>(p_rowptr, p_colidx, p_o1, p_o2, p_att, NN);

        float* xout = (l == 5) ? (float*)d_out : ((l & 1) ? p_x1 : p_x0);
        spmm_elu<<<dim3(NN, 1), 128>>>(p_rowptr, p_colidx, p_att, p_ho, xout, fout, fout);

        xin = xout;
    }
    (void)in_sizes; (void)n_in; (void)out_size;
}

// round 5
// speedup vs baseline: 2.3294x; 1.3158x over previous
#include <cuda_runtime.h>
#include <cuda_bf16.h>
#include <cuda_fp16.h>
#include <math.h>
#include <stdint.h>

#define NN 2048          // nodes
#define NH 8             // heads
#define ALPHA 0.2f
#define NNZ_CAP (2048*128)
#define HID_MAX 512
#define KSPLIT 8

// ---------------- scratch (static device allocations) ----------------
__device__ int   g_deg[NN];
__device__ int   g_rowptr[NN + 1];
__device__ int   g_colidx[NNZ_CAP];
__device__ __half g_h[NH * NN * HID_MAX];       // per-head projected features (fp16)
__device__ float g_s1[NH * NN];
__device__ float g_s2[NH * NN];
__device__ float g_att[(size_t)NH * NNZ_CAP];
__device__ float g_ho[NN * HID_MAX];
__device__ float g_o1[NN];
__device__ float g_o2[NN];
__device__ float g_part[KSPLIT * NN * 384];     // split-K partials for Wo gemm
// bf16 hi/lo operand buffers (A: activations, B: weights)
__device__ __nv_bfloat16 g_a1[NN * 4096];
__device__ __nv_bfloat16 g_a2[NN * 4096];
__device__ __nv_bfloat16 g_b1[1 << 21];
__device__ __nv_bfloat16 g_b2[1 << 21];

// ---------------- bf16 hi/lo elementwise split (weights + layer-0 x) ----------------
__global__ void split_bf(const float* __restrict__ in, __nv_bfloat16* __restrict__ o1,
                         __nv_bfloat16* __restrict__ o2, long n4) {
    long i = (long)blockIdx.x * blockDim.x + threadIdx.x;
    if (i >= n4) return;
    float4 v = ((const float4*)in)[i];
    __nv_bfloat16 h0 = __float2bfloat16_rn(v.x), h1 = __float2bfloat16_rn(v.y);
    __nv_bfloat16 h2 = __float2bfloat16_rn(v.z), h3 = __float2bfloat16_rn(v.w);
    __nv_bfloat16 l0 = __float2bfloat16_rn(v.x - __bfloat162float(h0));
    __nv_bfloat16 l1 = __float2bfloat16_rn(v.y - __bfloat162float(h1));
    __nv_bfloat16 l2 = __float2bfloat16_rn(v.z - __bfloat162float(h2));
    __nv_bfloat16 l3 = __float2bfloat16_rn(v.w - __bfloat162float(h3));
    ushort4 uh, ul;
    uh.x = *(unsigned short*)&h0; uh.y = *(unsigned short*)&h1;
    uh.z = *(unsigned short*)&h2; uh.w = *(unsigned short*)&h3;
    ul.x = *(unsigned short*)&l0; ul.y = *(unsigned short*)&l1;
    ul.z = *(unsigned short*)&l2; ul.w = *(unsigned short*)&l3;
    ((ushort4*)o1)[i] = uh;
    ((ushort4*)o2)[i] = ul;
}

// ---------------- HMMA bf16x2 GEMM ----------------
#define A_ST 40
#define B_ST 136
#define A_BYTES (128 * A_ST * 2)
#define B_BYTES (32 * B_ST * 2)
#define BUF_BYTES (2 * A_BYTES + 2 * B_BYTES)
#define GSMEM_BYTES (2 * BUF_BYTES)

__device__ __forceinline__ uint32_t smem_u32(const void* p) {
    uint32_t a;
    asm("{ .reg .u64 t; cvta.to.shared.u64 t, %1; cvt.u32.u64 %0, t; }" : "=r"(a) : "l"(p));
    return a;
}

#define LDMX4(r0, r1, r2, r3, addr) \
    asm volatile("ldmatrix.sync.aligned.m8n8.x4.shared.b16 {%0,%1,%2,%3}, [%4];" \
                 : "=r"(r0), "=r"(r1), "=r"(r2), "=r"(r3) : "r"(addr))
#define LDMX2T(r0, r1, addr) \
    asm volatile("ldmatrix.sync.aligned.m8n8.x2.trans.shared.b16 {%0,%1}, [%2];" \
                 : "=r"(r0), "=r"(r1) : "r"(addr))
#define MMA16816(acc, a, b) \
    asm volatile("mma.sync.aligned.m16n8k16.row.col.f32.bf16.bf16.f32 " \
                 "{%0,%1,%2,%3}, {%4,%5,%6,%7}, {%8,%9}, {%0,%1,%2,%3};" \
                 : "+f"((acc)[0]), "+f"((acc)[1]), "+f"((acc)[2]), "+f"((acc)[3]) \
                 : "r"((a)[0]), "r"((a)[1]), "r"((a)[2]), "r"((a)[3]), \
                   "r"((b)[0]), "r"((b)[1]))

__device__ __forceinline__ void store2(float* p, float x, float y) {
    *(float2*)p = make_float2(x, y);
}
__device__ __forceinline__ void store2(__half* p, float x, float y) {
    *(__half2*)p = __floats2half2_rn(x, y);
}

template <typename OT>
__global__ void __launch_bounds__(256, 1) gemm_mma(
    const __nv_bfloat16* __restrict__ A1, const __nv_bfloat16* __restrict__ A2,
    long lda, long sAz,
    const __nv_bfloat16* __restrict__ B1, const __nv_bfloat16* __restrict__ B2,
    long ldb, long sBz,
    OT* __restrict__ C, long ldc, long sCz, int Kc)
{
    extern __shared__ char sm[];
    int tid = threadIdx.x;
    int wid = tid >> 5, lane = tid & 31;
    int mBase = blockIdx.y * 128;
    int nBase = blockIdx.x * 128;
    int z = blockIdx.z;

    const __nv_bfloat16* a1 = A1 + (long)z * sAz + (size_t)mBase * lda;
    const __nv_bfloat16* a2 = A2 + (long)z * sAz + (size_t)mBase * lda;
    const __nv_bfloat16* b1 = B1 + (long)z * sBz + nBase;
    const __nv_bfloat16* b2 = B2 + (long)z * sBz + nBase;
    OT* c = C + (long)z * sCz;

    float acc[4][4][4];
#pragma unroll
    for (int i = 0; i < 4; i++)
#pragma unroll
        for (int j = 0; j < 4; j++)
#pragma unroll
            for (int r = 0; r < 4; r++) acc[i][j][r] = 0.f;

    int mW = (wid >> 2) * 64;
    int nW = (wid & 3) * 32;
    uint32_t sb = smem_u32(sm);
    uint4 ra1[2], ra2[2], rb1[2], rb2[2];

#pragma unroll
    for (int i = 0; i < 2; i++) {
        int cch = i * 256 + tid;
        int r = cch >> 2, ch = cch & 3;
        ra1[i] = *(const uint4*)((const char*)a1 + (size_t)r * lda * 2 + ch * 16);
        ra2[i] = *(const uint4*)((const char*)a2 + (size_t)r * lda * 2 + ch * 16);
        int rB = cch >> 4, chB = cch & 15;
        rb1[i] = *(const uint4*)((const char*)b1 + (size_t)rB * ldb * 2 + chB * 16);
        rb2[i] = *(const uint4*)((const char*)b2 + (size_t)rB * ldb * 2 + chB * 16);
    }
#pragma unroll
    for (int i = 0; i < 2; i++) {
        int cch = i * 256 + tid;
        int r = cch >> 2, ch = cch & 3;
        *(uint4*)(sm + r * (A_ST * 2) + ch * 16) = ra1[i];
        *(uint4*)(sm + A_BYTES + r * (A_ST * 2) + ch * 16) = ra2[i];
        int rB = cch >> 4, chB = cch & 15;
        *(uint4*)(sm + 2 * A_BYTES + rB * (B_ST * 2) + chB * 16) = rb1[i];
        *(uint4*)(sm + 2 * A_BYTES + B_BYTES + rB * (B_ST * 2) + chB * 16) = rb2[i];
    }
    __syncthreads();

    int nT = Kc >> 5;
    for (int t = 0; t < nT; t++) {
        if (t + 1 < nT) {
#pragma unroll
            for (int i = 0; i < 2; i++) {
                int cch = i * 256 + tid;
                int r = cch >> 2, ch = cch & 3;
                ra1[i] = *(const uint4*)((const char*)a1 + (size_t)r * lda * 2 + (t + 1) * 64 + ch * 16);
                ra2[i] = *(const uint4*)((const char*)a2 + (size_t)r * lda * 2 + (t + 1) * 64 + ch * 16);
                int rB = cch >> 4, chB = cch & 15;
                rb1[i] = *(const uint4*)((const char*)b1 + (size_t)((t + 1) * 32 + rB) * ldb * 2 + chB * 16);
                rb2[i] = *(const uint4*)((const char*)b2 + (size_t)((t + 1) * 32 + rB) * ldb * 2 + chB * 16);
            }
        }
        uint32_t bufb = sb + (uint32_t)(t & 1) * BUF_BYTES;
        uint32_t sA1 = bufb;
        uint32_t sA2 = bufb + A_BYTES;
        uint32_t sB1 = bufb + 2 * A_BYTES;
        uint32_t sB2 = bufb + 2 * A_BYTES + B_BYTES;

#pragma unroll
        for (int kk = 0; kk < 32; kk += 16) {
            uint32_t af[2][4][4];
            uint32_t bfr[2][4][2];
#pragma unroll
            for (int mt = 0; mt < 4; mt++) {
                uint32_t off = (uint32_t)((mW + mt * 16 + (lane & 15)) * (A_ST * 2)
                                          + (kk + ((lane >> 4) << 3)) * 2);
                LDMX4(af[0][mt][0], af[0][mt][1], af[0][mt][2], af[0][mt][3], sA1 + off);
                LDMX4(af[1][mt][0], af[1][mt][1], af[1][mt][2], af[1][mt][3], sA2 + off);
            }
#pragma unroll
            for (int nt = 0; nt < 4; nt++) {
                uint32_t off = (uint32_t)((kk + (lane & 15)) * (B_ST * 2) + (nW + nt * 8) * 2);
                LDMX2T(bfr[0][nt][0], bfr[0][nt][1], sB1 + off);
                LDMX2T(bfr[1][nt][0], bfr[1][nt][1], sB2 + off);
            }
#pragma unroll
            for (int mt = 0; mt < 4; mt++)
#pragma unroll
                for (int nt = 0; nt < 4; nt++) {
                    MMA16816(acc[mt][nt], af[0][mt], bfr[0][nt]);
                    MMA16816(acc[mt][nt], af[0][mt], bfr[1][nt]);
                    MMA16816(acc[mt][nt], af[1][mt], bfr[0][nt]);
                }
        }
        if (t + 1 < nT) {
            char* nb = sm + ((t + 1) & 1) * BUF_BYTES;
#pragma unroll
            for (int i = 0; i < 2; i++) {
                int cch = i * 256 + tid;
                int r = cch >> 2, ch = cch & 3;
                *(uint4*)(nb + r * (A_ST * 2) + ch * 16) = ra1[i];
                *(uint4*)(nb + A_BYTES + r * (A_ST * 2) + ch * 16) = ra2[i];
                int rB = cch >> 4, chB = cch & 15;
                *(uint4*)(nb + 2 * A_BYTES + rB * (B_ST * 2) + chB * 16) = rb1[i];
                *(uint4*)(nb + 2 * A_BYTES + B_BYTES + rB * (B_ST * 2) + chB * 16) = rb2[i];
            }
            __syncthreads();
        }
    }

#pragma unroll
    for (int mt = 0; mt < 4; mt++) {
        int row0 = mBase + mW + mt * 16 + (lane >> 2);
#pragma unroll
        for (int nt = 0; nt < 4; nt++) {
            int col = nBase + nW + nt * 8 + (lane & 3) * 2;
            OT* cr = c + (size_t)row0 * ldc + col;
            store2(cr, acc[mt][nt][0], acc[mt][nt][1]);
            store2(cr + 8 * ldc, acc[mt][nt][2], acc[mt][nt][3]);
        }
    }
}

// ---------------- CSR build ----------------
__global__ void csr_count(const float* __restrict__ adj, int* __restrict__ deg) {
    int row = blockIdx.x * (blockDim.x >> 5) + (threadIdx.x >> 5);
    if (row >= NN) return;
    int lane = threadIdx.x & 31;
    const float* r = adj + (size_t)row * NN;
    int cnt = 0;
    for (int c0 = 0; c0 < NN; c0 += 32) {
        float v = r[c0 + lane];
        unsigned m = __ballot_sync(0xffffffffu, v > 0.f);
        cnt += __popc(m);
    }
    if (lane == 0) deg[row] = cnt;
}

__global__ void csr_scan(const int* __restrict__ deg, int* __restrict__ rowptr) {
    __shared__ int s[1024];
    int t = threadIdx.x;
    int d0 = deg[2 * t], d1 = deg[2 * t + 1];
    s[t] = d0 + d1;
    __syncthreads();
    for (int off = 1; off < 1024; off <<= 1) {
        int v = s[t];
        int add = (t >= off) ? s[t - off] : 0;
        __syncthreads();
        s[t] = v + add;
        __syncthreads();
    }
    int excl = (t > 0) ? s[t - 1] : 0;
    rowptr[2 * t]     = excl;
    rowptr[2 * t + 1] = excl + d0;
    if (t == 1023) rowptr[NN] = s[1023];
}

__global__ void csr_fill(const float* __restrict__ adj, const int* __restrict__ rowptr,
                         int* __restrict__ colidx) {
    int row = blockIdx.x * (blockDim.x >> 5) + (threadIdx.x >> 5);
    if (row >= NN) return;
    int lane = threadIdx.x & 31;
    const float* r = adj + (size_t)row * NN;
    int pos = rowptr[row];
    for (int c0 = 0; c0 < NN; c0 += 32) {
        float v = r[c0 + lane];
        unsigned m = __ballot_sync(0xffffffffu, v > 0.f);
        if (v > 0.f) {
            int off = __popc(m & ((1u << lane) - 1u));
            colidx[pos + off] = c0 + lane;
        }
        pos += __popc(m);
    }
}

// Deterministic split-K reduction
__global__ void reduce_split(const float* __restrict__ part, float* __restrict__ out, int MN) {
    int i = (blockIdx.x * blockDim.x + threadIdx.x) << 2;
    if (i >= MN) return;
    float4 s = make_float4(0.f, 0.f, 0.f, 0.f);
#pragma unroll
    for (int p = 0; p < KSPLIT; p++) {
        float4 v = *(const float4*)&part[(size_t)p * MN + i];
        s.x += v.x; s.y += v.y; s.z += v.z; s.w += v.w;
    }
    *(float4*)&out[i] = s;
}

// ---------------- s1/s2 dot products (half h) ----------------
__global__ void dot_s_h(const __half* __restrict__ h, const float* __restrict__ a,
                        float* __restrict__ s1, float* __restrict__ s2, int hid, int total) {
    int w = (blockIdx.x * blockDim.x + threadIdx.x) >> 5;
    if (w >= total) return;
    int lane = threadIdx.x & 31;
    int head = w / NN;
    const __half2* hp = (const __half2*)(h + (size_t)w * hid);
    const float* a1 = a + (size_t)head * 2 * hid;
    const float* a2 = a1 + hid;
    int hw = hid >> 1;
    float v1 = 0.f, v2 = 0.f;
    for (int d = lane; d < hw; d += 32) {
        float2 x = __half22float2(hp[d]);
        float2 w1 = *(const float2*)&a1[2 * d];
        float2 w2 = *(const float2*)&a2[2 * d];
        v1 += x.x * w1.x + x.y * w1.y;
        v2 += x.x * w2.x + x.y * w2.y;
    }
#pragma unroll
    for (int o = 16; o; o >>= 1) {
        v1 += __shfl_xor_sync(0xffffffffu, v1, o);
        v2 += __shfl_xor_sync(0xffffffffu, v2, o);
    }
    if (lane == 0) { s1[w] = v1; s2[w] = v2; }
}

// ---------------- o1/o2 dot products (fp32 ho) ----------------
__global__ void dot_s_f(const float* __restrict__ h, const float* __restrict__ a,
                        float* __restrict__ s1, float* __restrict__ s2, int hid, int total) {
    int w = (blockIdx.x * blockDim.x + threadIdx.x) >> 5;
    if (w >= total) return;
    int lane = threadIdx.x & 31;
    const float* hp = h + (size_t)w * hid;
    const float* a1 = a;
    const float* a2 = a + hid;
    float v1 = 0.f, v2 = 0.f;
    for (int d = lane; d < hid; d += 32) {
        float x = hp[d];
        v1 += x * a1[d];
        v2 += x * a2[d];
    }
#pragma unroll
    for (int o = 16; o; o >>= 1) {
        v1 += __shfl_xor_sync(0xffffffffu, v1, o);
        v2 += __shfl_xor_sync(0xffffffffu, v2, o);
    }
    if (lane == 0) { s1[w] = v1; s2[w] = v2; }
}

// ---------------- masked softmax over neighbor lists ----------------
__global__ void att_softmax(const int* __restrict__ rowptr, const int* __restrict__ colidx,
                            const float* __restrict__ s1, const float* __restrict__ s2,
                            float* __restrict__ att, int total) {
    int w = (blockIdx.x * blockDim.x + threadIdx.x) >> 5;
    if (w >= total) return;
    int lane = threadIdx.x & 31;
    int head = w / NN;
    int i = w - head * NN;
    int b = rowptr[i], e = rowptr[i + 1];
    const float* s2h = s2 + (size_t)head * NN;
    float si = s1[w];
    float m = -1e30f;
    for (int k = b + lane; k < e; k += 32) {
        float v = si + s2h[colidx[k]];
        v = v > 0.f ? v : ALPHA * v;
        m = fmaxf(m, v);
    }
#pragma unroll
    for (int o = 16; o; o >>= 1) m = fmaxf(m, __shfl_xor_sync(0xffffffffu, m, o));
    float sum = 0.f;
    float* ah = att + (size_t)head * NNZ_CAP;
    for (int k = b + lane; k < e; k += 32) {
        float v = si + s2h[colidx[k]];
        v = v > 0.f ? v : ALPHA * v;
        float ex = expf(v - m);
        ah[k] = ex;
        sum += ex;
    }
#pragma unroll
    for (int o = 16; o; o >>= 1) sum += __shfl_xor_sync(0xffffffffu, sum, o);
    float inv = 1.f / sum;
    for (int k = b + lane; k < e; k += 32) ah[k] *= inv;
}

// ---------------- helpers ----------------
__device__ __forceinline__ float elu1(float x) { return x > 0.f ? x : expm1f(x); }

__device__ __forceinline__ void write_bf_pair(__nv_bfloat16* o1, __nv_bfloat16* o2,
                                              size_t idx, float x, float y) {
    // write two consecutive bf16 hi and lo values as one 4B store each
    __nv_bfloat16 hx = __float2bfloat16_rn(x), hy = __float2bfloat16_rn(y);
    __nv_bfloat16 lx = __float2bfloat16_rn(x - __bfloat162float(hx));
    __nv_bfloat16 ly = __float2bfloat16_rn(y - __bfloat162float(hy));
    uint32_t hv = (uint32_t)*(unsigned short*)&hx | ((uint32_t)*(unsigned short*)&hy << 16);
    uint32_t lv = (uint32_t)*(unsigned short*)&lx | ((uint32_t)*(unsigned short*)&ly << 16);
    *(uint32_t*)(o1 + idx) = hv;
    *(uint32_t*)(o2 + idx) = lv;
}

// ---------------- head SpMM: hcat = elu(att @ h), half gather, bf16-pair out ----------------
__global__ void spmm_h(const int* __restrict__ rowptr, const int* __restrict__ colidx,
                       const float* __restrict__ att, const __half* __restrict__ h,
                       __nv_bfloat16* __restrict__ o1, __nv_bfloat16* __restrict__ o2,
                       int hid, int out_stride) {
    int i = blockIdx.x, head = blockIdx.y;
    int tid = threadIdx.x;                    // 128
    int b = rowptr[i], e = rowptr[i + 1];
    int hw = hid >> 1;                        // half2 per row (64..256)
    const __half2* hb = (const __half2*)(h + (size_t)head * NN * hid);
    const float* av = att + (size_t)head * NNZ_CAP;
    bool c0 = tid < hw;
    bool c1 = tid + 128 < hw;
    float x0 = 0.f, y0 = 0.f, x1 = 0.f, y1 = 0.f;
#pragma unroll 4
    for (int k = b; k < e; k++) {
        int j = colidx[k];
        float a = __ldg(&av[k]);
        const __half2* hr = hb + (size_t)j * hw;
        if (c0) {
            float2 v = __half22float2(hr[tid]);
            x0 += a * v.x; y0 += a * v.y;
        }
        if (c1) {
            float2 v = __half22float2(hr[tid + 128]);
            x1 += a * v.x; y1 += a * v.y;
        }
    }
    size_t base = (size_t)i * out_stride + (size_t)head * hid;
    if (c0) write_bf_pair(o1, o2, base + 2 * tid, elu1(x0), elu1(y0));
    if (c1) write_bf_pair(o1, o2, base + 2 * (tid + 128), elu1(x1), elu1(y1));
}

// ---------------- output SpMM: x' = elu(ato @ ho); bf16-pair and/or fp32 out ----------------
__global__ void spmm_out(const int* __restrict__ rowptr, const int* __restrict__ colidx,
                         const float* __restrict__ att, const float* __restrict__ ho,
                         __nv_bfloat16* __restrict__ o1, __nv_bfloat16* __restrict__ o2,
                         float* __restrict__ ofp, int hid) {
    int i = blockIdx.x;
    int tid = threadIdx.x;                    // 128, handles 2 consecutive elems
    int b = rowptr[i], e = rowptr[i + 1];
    int hw = hid >> 1;
    bool c0 = tid < hw;
    bool c1 = tid + 128 < hw;
    float x0 = 0.f, y0 = 0.f, x1 = 0.f, y1 = 0.f;
#pragma unroll 4
    for (int k = b; k < e; k++) {
        int j = colidx[k];
        float a = __ldg(&att[k]);
        const float2* hr = (const float2*)(ho + (size_t)j * hid);
        if (c0) {
            float2 v = hr[tid];
            x0 += a * v.x; y0 += a * v.y;
        }
        if (c1) {
            float2 v = hr[tid + 128];
            x1 += a * v.x; y1 += a * v.y;
        }
    }
    size_t base = (size_t)i * hid;
    if (c0) {
        float ex = elu1(x0), ey = elu1(y0);
        if (ofp) *(float2*)(ofp + base + 2 * tid) = make_float2(ex, ey);
        else     write_bf_pair(o1, o2, base + 2 * tid, ex, ey);
    }
    if (c1) {
        float ex = elu1(x1), ey = elu1(y1);
        if (ofp) *(float2*)(ofp + base + 2 * (tid + 128)) = make_float2(ex, ey);
        else     write_bf_pair(o1, o2, base + 2 * (tid + 128), ex, ey);
    }
}

// ---------------- host side ----------------
struct LayerDims { int fin, hid, fout; };
static const LayerDims g_dims[6] = {
    {256, 128, 128}, {128, 256, 256}, {256, 512, 384},
    {384, 512, 256}, {256, 256, 128}, {128, 128, 256}
};

extern "C" void kernel_launch(void* const* d_in, const int* in_sizes, int n_in,
                              void* d_out, int out_size) {
    const float* x   = (const float*)d_in[0];
    const float* adj = (const float*)d_in[1];

    float *p_s1, *p_s2, *p_att, *p_ho, *p_o1v, *p_o2v, *p_part;
    int *p_deg, *p_rowptr, *p_colidx;
    __half* p_h;
    __nv_bfloat16 *p_a1, *p_a2, *p_b1, *p_b2;
    cudaGetSymbolAddress((void**)&p_deg, g_deg);
    cudaGetSymbolAddress((void**)&p_rowptr, g_rowptr);
    cudaGetSymbolAddress((void**)&p_colidx, g_colidx);
    cudaGetSymbolAddress((void**)&p_h, g_h);
    cudaGetSymbolAddress((void**)&p_s1, g_s1);
    cudaGetSymbolAddress((void**)&p_s2, g_s2);
    cudaGetSymbolAddress((void**)&p_att, g_att);
    cudaGetSymbolAddress((void**)&p_ho, g_ho);
    cudaGetSymbolAddress((void**)&p_o1v, g_o1);
    cudaGetSymbolAddress((void**)&p_o2v, g_o2);
    cudaGetSymbolAddress((void**)&p_part, g_part);
    cudaGetSymbolAddress((void**)&p_a1, g_a1);
    cudaGetSymbolAddress((void**)&p_a2, g_a2);
    cudaGetSymbolAddress((void**)&p_b1, g_b1);
    cudaGetSymbolAddress((void**)&p_b2, g_b2);

    static int smem_set = 0;
    if (!smem_set) {
        cudaFuncSetAttribute(gemm_mma<float>, cudaFuncAttributeMaxDynamicSharedMemorySize, GSMEM_BYTES);
        cudaFuncSetAttribute(gemm_mma<__half>, cudaFuncAttributeMaxDynamicSharedMemorySize, GSMEM_BYTES);
        smem_set = 1;
    }

    // Build CSR of adjacency
    csr_count<<<NN / 8, 256>>>(adj, p_deg);
    csr_scan<<<1, 1024>>>(p_deg, p_rowptr);
    csr_fill<<<NN / 8, 256>>>(adj, p_rowptr, p_colidx);

    // layer-0 activations: split x into bf16 hi/lo
    split_bf<<<(NN * 256 / 4 + 255) / 256, 256>>>(x, p_a1, p_a2, NN * 256 / 4);

    for (int l = 0; l < 6; l++) {
        int fin = g_dims[l].fin, hid = g_dims[l].hid, fout = g_dims[l].fout;
        const float* Wh = (const float*)d_in[2 + 4 * l];
        const float* ah = (const float*)d_in[3 + 4 * l];
        const float* Wo = (const float*)d_in[4 + 4 * l];
        const float* ao = (const float*)d_in[5 + 4 * l];

        // ---- head GEMM: h[head] = x @ Wh[head], bf16x2 HMMA, fp16 output ----
        split_bf<<<((long)NH * fin * hid / 4 + 255) / 256, 256>>>(Wh, p_b1, p_b2, (long)NH * fin * hid / 4);
        gemm_mma<__half><<<dim3(hid / 128, NN / 128, NH), 256, GSMEM_BYTES>>>(
            p_a1, p_a2, fin, 0L,
            p_b1, p_b2, hid, (long)fin * hid,
            p_h, hid, (long)NN * hid, fin);

        // s1/s2, softmax, head SpMM (writes hcat bf16 hi/lo -> Wo A operands)
        int totalHN = NH * NN;
        dot_s_h<<<(totalHN * 32 + 255) / 256, 256>>>(p_h, ah, p_s1, p_s2, hid, totalHN);
        att_softmax<<<(totalHN * 32 + 255) / 256, 256>>>(p_rowptr, p_colidx, p_s1, p_s2, p_att, totalHN);
        spmm_h<<<dim3(NN, NH), 128>>>(p_rowptr, p_colidx, p_att, p_h, p_a1, p_a2, hid, NH * hid);

        // ---- output GEMM: ho = hcat @ Wo, bf16x2 HMMA split-K ----
        int Ktot = NH * hid;
        int Kc = Ktot / KSPLIT;
        split_bf<<<((long)Ktot * fout / 4 + 255) / 256, 256>>>(Wo, p_b1, p_b2, (long)Ktot * fout / 4);
        gemm_mma<float><<<dim3(fout / 128, NN / 128, KSPLIT), 256, GSMEM_BYTES>>>(
            p_a1, p_a2, Ktot, (long)Kc,
            p_b1, p_b2, fout, (long)Kc * fout,
            p_part, fout, (long)NN * fout, Kc);
        reduce_split<<<(NN * fout / 4 + 255) / 256, 256>>>(p_part, p_ho, NN * fout);

        dot_s_f<<<(NN * 32 + 255) / 256, 256>>>(p_ho, ao, p_o1v, p_o2v, fout, NN);
        att_softmax<<<(NN * 32 + 255) / 256, 256>>>(p_rowptr, p_colidx, p_o1v, p_o2v, p_att, NN);

        // next x: bf16 hi/lo into A buffers (layers 0-4), fp32 d_out at layer 5
        float* ofp = (l == 5) ? (float*)d_out : nullptr;
        spmm_out<<<NN, 128>>>(p_rowptr, p_colidx, p_att, p_ho, p_a1, p_a2, ofp, fout);
    }
    (void)in_sizes; (void)n_in; (void)out_size;
}

// round 6
// speedup vs baseline: 2.6554x; 1.1399x over previous
#include <cuda_runtime.h>
#include <cuda_bf16.h>
#include <cuda_fp16.h>
#include <math.h>
#include <stdint.h>

#define NN 2048          // nodes
#define NH 8             // heads
#define ALPHA 0.2f
#define NNZ_CAP (2048*128)
#define HID_MAX 512
#define KSPLIT 8
#define DEG_CAP 1024

// ---------------- scratch (static device allocations) ----------------
__device__ int   g_deg[NN];
__device__ int   g_rowptr[NN + 1];
__device__ int   g_colidx[NNZ_CAP];
__device__ __half g_h[NH * NN * HID_MAX];       // per-head projected features (fp16)
__device__ float g_s1[NH * NN];
__device__ float g_s2[NH * NN];
__device__ float g_ho[NN * HID_MAX];
__device__ float g_o1[NN];
__device__ float g_o2[NN];
__device__ float g_part[KSPLIT * NN * 384];     // split-K partials for Wo gemm
// bf16 hi/lo operand buffers (A: activations; B: ALL weights, pre-split once)
__device__ __nv_bfloat16 g_a1[NN * 4096];
__device__ __nv_bfloat16 g_a2[NN * 4096];
__device__ __nv_bfloat16 g_b1[1 << 23];
__device__ __nv_bfloat16 g_b2[1 << 23];

// ---------------- bf16 hi/lo elementwise split (layer-0 x) ----------------
__device__ __forceinline__ void split4(float4 v, ushort4& uh, ushort4& ul) {
    __nv_bfloat16 h0 = __float2bfloat16_rn(v.x), h1 = __float2bfloat16_rn(v.y);
    __nv_bfloat16 h2 = __float2bfloat16_rn(v.z), h3 = __float2bfloat16_rn(v.w);
    __nv_bfloat16 l0 = __float2bfloat16_rn(v.x - __bfloat162float(h0));
    __nv_bfloat16 l1 = __float2bfloat16_rn(v.y - __bfloat162float(h1));
    __nv_bfloat16 l2 = __float2bfloat16_rn(v.z - __bfloat162float(h2));
    __nv_bfloat16 l3 = __float2bfloat16_rn(v.w - __bfloat162float(h3));
    uh.x = *(unsigned short*)&h0; uh.y = *(unsigned short*)&h1;
    uh.z = *(unsigned short*)&h2; uh.w = *(unsigned short*)&h3;
    ul.x = *(unsigned short*)&l0; ul.y = *(unsigned short*)&l1;
    ul.z = *(unsigned short*)&l2; ul.w = *(unsigned short*)&l3;
}

__global__ void split_bf(const float* __restrict__ in, __nv_bfloat16* __restrict__ o1,
                         __nv_bfloat16* __restrict__ o2, long n4) {
    long i = (long)blockIdx.x * blockDim.x + threadIdx.x;
    if (i >= n4) return;
    ushort4 uh, ul;
    split4(((const float4*)in)[i], uh, ul);
    ((ushort4*)o1)[i] = uh;
    ((ushort4*)o2)[i] = ul;
}

// ---------------- batched weight split: all 12 weight tensors in one launch ----------------
struct WEnt { const float* src; long off4; long n4; };
struct WTab { WEnt e[12]; };

__global__ void split_bf_batch(WTab tab, __nv_bfloat16* __restrict__ o1,
                               __nv_bfloat16* __restrict__ o2) {
    WEnt en = tab.e[blockIdx.y];
    long i = (long)blockIdx.x * blockDim.x + threadIdx.x;
    if (i >= en.n4) return;
    ushort4 uh, ul;
    split4(((const float4*)en.src)[i], uh, ul);
    ((ushort4*)o1)[en.off4 + i] = uh;
    ((ushort4*)o2)[en.off4 + i] = ul;
}

// ---------------- HMMA bf16x2 GEMM ----------------
#define A_ST 40
#define B_ST 136
#define A_BYTES (128 * A_ST * 2)
#define B_BYTES (32 * B_ST * 2)
#define BUF_BYTES (2 * A_BYTES + 2 * B_BYTES)
#define GSMEM_BYTES (2 * BUF_BYTES)

__device__ __forceinline__ uint32_t smem_u32(const void* p) {
    uint32_t a;
    asm("{ .reg .u64 t; cvta.to.shared.u64 t, %1; cvt.u32.u64 %0, t; }" : "=r"(a) : "l"(p));
    return a;
}

#define LDMX4(r0, r1, r2, r3, addr) \
    asm volatile("ldmatrix.sync.aligned.m8n8.x4.shared.b16 {%0,%1,%2,%3}, [%4];" \
                 : "=r"(r0), "=r"(r1), "=r"(r2), "=r"(r3) : "r"(addr))
#define LDMX2T(r0, r1, addr) \
    asm volatile("ldmatrix.sync.aligned.m8n8.x2.trans.shared.b16 {%0,%1}, [%2];" \
                 : "=r"(r0), "=r"(r1) : "r"(addr))
#define MMA16816(acc, a, b) \
    asm volatile("mma.sync.aligned.m16n8k16.row.col.f32.bf16.bf16.f32 " \
                 "{%0,%1,%2,%3}, {%4,%5,%6,%7}, {%8,%9}, {%0,%1,%2,%3};" \
                 : "+f"((acc)[0]), "+f"((acc)[1]), "+f"((acc)[2]), "+f"((acc)[3]) \
                 : "r"((a)[0]), "r"((a)[1]), "r"((a)[2]), "r"((a)[3]), \
                   "r"((b)[0]), "r"((b)[1]))

__device__ __forceinline__ void store2(float* p, float x, float y) {
    *(float2*)p = make_float2(x, y);
}
__device__ __forceinline__ void store2(__half* p, float x, float y) {
    *(__half2*)p = __floats2half2_rn(x, y);
}

template <typename OT>
__global__ void __launch_bounds__(256, 1) gemm_mma(
    const __nv_bfloat16* __restrict__ A1, const __nv_bfloat16* __restrict__ A2,
    long lda, long sAz,
    const __nv_bfloat16* __restrict__ B1, const __nv_bfloat16* __restrict__ B2,
    long ldb, long sBz,
    OT* __restrict__ C, long ldc, long sCz, int Kc)
{
    extern __shared__ char sm[];
    int tid = threadIdx.x;
    int wid = tid >> 5, lane = tid & 31;
    int mBase = blockIdx.y * 128;
    int nBase = blockIdx.x * 128;
    int z = blockIdx.z;

    const __nv_bfloat16* a1 = A1 + (long)z * sAz + (size_t)mBase * lda;
    const __nv_bfloat16* a2 = A2 + (long)z * sAz + (size_t)mBase * lda;
    const __nv_bfloat16* b1 = B1 + (long)z * sBz + nBase;
    const __nv_bfloat16* b2 = B2 + (long)z * sBz + nBase;
    OT* c = C + (long)z * sCz;

    float acc[4][4][4];
#pragma unroll
    for (int i = 0; i < 4; i++)
#pragma unroll
        for (int j = 0; j < 4; j++)
#pragma unroll
            for (int r = 0; r < 4; r++) acc[i][j][r] = 0.f;

    int mW = (wid >> 2) * 64;
    int nW = (wid & 3) * 32;
    uint32_t sb = smem_u32(sm);
    uint4 ra1[2], ra2[2], rb1[2], rb2[2];

#pragma unroll
    for (int i = 0; i < 2; i++) {
        int cch = i * 256 + tid;
        int r = cch >> 2, ch = cch & 3;
        ra1[i] = *(const uint4*)((const char*)a1 + (size_t)r * lda * 2 + ch * 16);
        ra2[i] = *(const uint4*)((const char*)a2 + (size_t)r * lda * 2 + ch * 16);
        int rB = cch >> 4, chB = cch & 15;
        rb1[i] = *(const uint4*)((const char*)b1 + (size_t)rB * ldb * 2 + chB * 16);
        rb2[i] = *(const uint4*)((const char*)b2 + (size_t)rB * ldb * 2 + chB * 16);
    }
#pragma unroll
    for (int i = 0; i < 2; i++) {
        int cch = i * 256 + tid;
        int r = cch >> 2, ch = cch & 3;
        *(uint4*)(sm + r * (A_ST * 2) + ch * 16) = ra1[i];
        *(uint4*)(sm + A_BYTES + r * (A_ST * 2) + ch * 16) = ra2[i];
        int rB = cch >> 4, chB = cch & 15;
        *(uint4*)(sm + 2 * A_BYTES + rB * (B_ST * 2) + chB * 16) = rb1[i];
        *(uint4*)(sm + 2 * A_BYTES + B_BYTES + rB * (B_ST * 2) + chB * 16) = rb2[i];
    }
    __syncthreads();

    int nT = Kc >> 5;
    for (int t = 0; t < nT; t++) {
        if (t + 1 < nT) {
#pragma unroll
            for (int i = 0; i < 2; i++) {
                int cch = i * 256 + tid;
                int r = cch >> 2, ch = cch & 3;
                ra1[i] = *(const uint4*)((const char*)a1 + (size_t)r * lda * 2 + (t + 1) * 64 + ch * 16);
                ra2[i] = *(const uint4*)((const char*)a2 + (size_t)r * lda * 2 + (t + 1) * 64 + ch * 16);
                int rB = cch >> 4, chB = cch & 15;
                rb1[i] = *(const uint4*)((const char*)b1 + (size_t)((t + 1) * 32 + rB) * ldb * 2 + chB * 16);
                rb2[i] = *(const uint4*)((const char*)b2 + (size_t)((t + 1) * 32 + rB) * ldb * 2 + chB * 16);
            }
        }
        uint32_t bufb = sb + (uint32_t)(t & 1) * BUF_BYTES;
        uint32_t sA1 = bufb;
        uint32_t sA2 = bufb + A_BYTES;
        uint32_t sB1 = bufb + 2 * A_BYTES;
        uint32_t sB2 = bufb + 2 * A_BYTES + B_BYTES;

#pragma unroll
        for (int kk = 0; kk < 32; kk += 16) {
            uint32_t af[2][4][4];
            uint32_t bfr[2][4][2];
#pragma unroll
            for (int mt = 0; mt < 4; mt++) {
                uint32_t off = (uint32_t)((mW + mt * 16 + (lane & 15)) * (A_ST * 2)
                                          + (kk + ((lane >> 4) << 3)) * 2);
                LDMX4(af[0][mt][0], af[0][mt][1], af[0][mt][2], af[0][mt][3], sA1 + off);
                LDMX4(af[1][mt][0], af[1][mt][1], af[1][mt][2], af[1][mt][3], sA2 + off);
            }
#pragma unroll
            for (int nt = 0; nt < 4; nt++) {
                uint32_t off = (uint32_t)((kk + (lane & 15)) * (B_ST * 2) + (nW + nt * 8) * 2);
                LDMX2T(bfr[0][nt][0], bfr[0][nt][1], sB1 + off);
                LDMX2T(bfr[1][nt][0], bfr[1][nt][1], sB2 + off);
            }
#pragma unroll
            for (int mt = 0; mt < 4; mt++)
#pragma unroll
                for (int nt = 0; nt < 4; nt++) {
                    MMA16816(acc[mt][nt], af[0][mt], bfr[0][nt]);
                    MMA16816(acc[mt][nt], af[0][mt], bfr[1][nt]);
                    MMA16816(acc[mt][nt], af[1][mt], bfr[0][nt]);
                }
        }
        if (t + 1 < nT) {
            char* nb = sm + ((t + 1) & 1) * BUF_BYTES;
#pragma unroll
            for (int i = 0; i < 2; i++) {
                int cch = i * 256 + tid;
                int r = cch >> 2, ch = cch & 3;
                *(uint4*)(nb + r * (A_ST * 2) + ch * 16) = ra1[i];
                *(uint4*)(nb + A_BYTES + r * (A_ST * 2) + ch * 16) = ra2[i];
                int rB = cch >> 4, chB = cch & 15;
                *(uint4*)(nb + 2 * A_BYTES + rB * (B_ST * 2) + chB * 16) = rb1[i];
                *(uint4*)(nb + 2 * A_BYTES + B_BYTES + rB * (B_ST * 2) + chB * 16) = rb2[i];
            }
            __syncthreads();
        }
    }

#pragma unroll
    for (int mt = 0; mt < 4; mt++) {
        int row0 = mBase + mW + mt * 16 + (lane >> 2);
#pragma unroll
        for (int nt = 0; nt < 4; nt++) {
            int col = nBase + nW + nt * 8 + (lane & 3) * 2;
            OT* cr = c + (size_t)row0 * ldc + col;
            store2(cr, acc[mt][nt][0], acc[mt][nt][1]);
            store2(cr + 8 * ldc, acc[mt][nt][2], acc[mt][nt][3]);
        }
    }
}

// ---------------- CSR build ----------------
__global__ void csr_count(const float* __restrict__ adj, int* __restrict__ deg) {
    int row = blockIdx.x * (blockDim.x >> 5) + (threadIdx.x >> 5);
    if (row >= NN) return;
    int lane = threadIdx.x & 31;
    const float* r = adj + (size_t)row * NN;
    int cnt = 0;
    for (int c0 = 0; c0 < NN; c0 += 32) {
        float v = r[c0 + lane];
        unsigned m = __ballot_sync(0xffffffffu, v > 0.f);
        cnt += __popc(m);
    }
    if (lane == 0) deg[row] = cnt;
}

__global__ void csr_scan(const int* __restrict__ deg, int* __restrict__ rowptr) {
    __shared__ int s[1024];
    int t = threadIdx.x;
    int d0 = deg[2 * t], d1 = deg[2 * t + 1];
    s[t] = d0 + d1;
    __syncthreads();
    for (int off = 1; off < 1024; off <<= 1) {
        int v = s[t];
        int add = (t >= off) ? s[t - off] : 0;
        __syncthreads();
        s[t] = v + add;
        __syncthreads();
    }
    int excl = (t > 0) ? s[t - 1] : 0;
    rowptr[2 * t]     = excl;
    rowptr[2 * t + 1] = excl + d0;
    if (t == 1023) rowptr[NN] = s[1023];
}

__global__ void csr_fill(const float* __restrict__ adj, const int* __restrict__ rowptr,
                         int* __restrict__ colidx) {
    int row = blockIdx.x * (blockDim.x >> 5) + (threadIdx.x >> 5);
    if (row >= NN) return;
    int lane = threadIdx.x & 31;
    const float* r = adj + (size_t)row * NN;
    int pos = rowptr[row];
    for (int c0 = 0; c0 < NN; c0 += 32) {
        float v = r[c0 + lane];
        unsigned m = __ballot_sync(0xffffffffu, v > 0.f);
        if (v > 0.f) {
            int off = __popc(m & ((1u << lane) - 1u));
            colidx[pos + off] = c0 + lane;
        }
        pos += __popc(m);
    }
}

// ---------------- s1/s2 dot products (half h) ----------------
__global__ void dot_s_h(const __half* __restrict__ h, const float* __restrict__ a,
                        float* __restrict__ s1, float* __restrict__ s2, int hid, int total) {
    int w = (blockIdx.x * blockDim.x + threadIdx.x) >> 5;
    if (w >= total) return;
    int lane = threadIdx.x & 31;
    int head = w / NN;
    const __half2* hp = (const __half2*)(h + (size_t)w * hid);
    const float* a1 = a + (size_t)head * 2 * hid;
    const float* a2 = a1 + hid;
    int hw = hid >> 1;
    float v1 = 0.f, v2 = 0.f;
    for (int d = lane; d < hw; d += 32) {
        float2 x = __half22float2(hp[d]);
        float2 w1 = *(const float2*)&a1[2 * d];
        float2 w2 = *(const float2*)&a2[2 * d];
        v1 += x.x * w1.x + x.y * w1.y;
        v2 += x.x * w2.x + x.y * w2.y;
    }
#pragma unroll
    for (int o = 16; o; o >>= 1) {
        v1 += __shfl_xor_sync(0xffffffffu, v1, o);
        v2 += __shfl_xor_sync(0xffffffffu, v2, o);
    }
    if (lane == 0) { s1[w] = v1; s2[w] = v2; }
}

// ---------------- fused split-K reduce + o1/o2 dot (block per node) ----------------
__global__ void reduce_dot(const float* __restrict__ part, const float* __restrict__ ao,
                           float* __restrict__ ho, float* __restrict__ o1,
                           float* __restrict__ o2, int fout) {
    __shared__ float rbuf[8];
    int i = blockIdx.x;
    int tid = threadIdx.x;                  // 128
    int wid = tid >> 5, lane = tid & 31;
    size_t MN = (size_t)NN * fout;
    float v1 = 0.f, v2 = 0.f;
    for (int c = tid; c < fout; c += 128) {
        size_t idx = (size_t)i * fout + c;
        float s = 0.f;
#pragma unroll
        for (int p = 0; p < KSPLIT; p++) s += part[(size_t)p * MN + idx];
        ho[idx] = s;
        v1 += s * ao[c];
        v2 += s * ao[fout + c];
    }
#pragma unroll
    for (int o = 16; o; o >>= 1) {
        v1 += __shfl_xor_sync(0xffffffffu, v1, o);
        v2 += __shfl_xor_sync(0xffffffffu, v2, o);
    }
    if (lane == 0) { rbuf[wid] = v1; rbuf[4 + wid] = v2; }
    __syncthreads();
    if (tid == 0) {
        o1[i] = rbuf[0] + rbuf[1] + rbuf[2] + rbuf[3];
        o2[i] = rbuf[4] + rbuf[5] + rbuf[6] + rbuf[7];
    }
}

// ---------------- helpers ----------------
__device__ __forceinline__ float elu1(float x) { return x > 0.f ? x : expm1f(x); }

__device__ __forceinline__ void write_bf_pair(__nv_bfloat16* o1, __nv_bfloat16* o2,
                                              size_t idx, float x, float y) {
    __nv_bfloat16 hx = __float2bfloat16_rn(x), hy = __float2bfloat16_rn(y);
    __nv_bfloat16 lx = __float2bfloat16_rn(x - __bfloat162float(hx));
    __nv_bfloat16 ly = __float2bfloat16_rn(y - __bfloat162float(hy));
    uint32_t hv = (uint32_t)*(unsigned short*)&hx | ((uint32_t)*(unsigned short*)&hy << 16);
    uint32_t lv = (uint32_t)*(unsigned short*)&lx | ((uint32_t)*(unsigned short*)&ly << 16);
    *(uint32_t*)(o1 + idx) = hv;
    *(uint32_t*)(o2 + idx) = lv;
}

// block softmax over neighbor list: fills ex[] (normalized weights premultiplied later),
// returns inv-sum; cj[] holds cached column indices. 128 threads.
__device__ __forceinline__ int block_softmax(const int* __restrict__ rowptr,
                                             const int* __restrict__ colidx,
                                             float si, const float* __restrict__ s2,
                                             int i, float* ex, int* cj, float& inv) {
    __shared__ float rbuf[8];
    int tid = threadIdx.x;
    int wid = tid >> 5, lane = tid & 31;
    int b = rowptr[i];
    int d = rowptr[i + 1] - b;
    if (d > DEG_CAP) d = DEG_CAP;
    float lm = -1e30f;
    for (int k = tid; k < d; k += 128) {
        int j = colidx[b + k];
        cj[k] = j;
        float v = si + s2[j];
        v = v > 0.f ? v : ALPHA * v;
        ex[k] = v;
        lm = fmaxf(lm, v);
    }
#pragma unroll
    for (int o = 16; o; o >>= 1) lm = fmaxf(lm, __shfl_xor_sync(0xffffffffu, lm, o));
    if (lane == 0) rbuf[wid] = lm;
    __syncthreads();
    float m = fmaxf(fmaxf(rbuf[0], rbuf[1]), fmaxf(rbuf[2], rbuf[3]));
    float ls = 0.f;
    for (int k = tid; k < d; k += 128) {
        float t = expf(ex[k] - m);
        ex[k] = t;
        ls += t;
    }
#pragma unroll
    for (int o = 16; o; o >>= 1) ls += __shfl_xor_sync(0xffffffffu, ls, o);
    if (lane == 0) rbuf[4 + wid] = ls;
    __syncthreads();
    inv = 1.f / (rbuf[4] + rbuf[5] + rbuf[6] + rbuf[7]);
    return d;
}

// ---------------- fused head softmax + SpMM: hcat = elu(softmax @ h) ----------------
__global__ void spmm_h_fused(const int* __restrict__ rowptr, const int* __restrict__ colidx,
                             const float* __restrict__ s1, const float* __restrict__ s2,
                             const __half* __restrict__ h,
                             __nv_bfloat16* __restrict__ o1, __nv_bfloat16* __restrict__ o2,
                             int hid, int out_stride) {
    __shared__ float ex[DEG_CAP];
    __shared__ int cj[DEG_CAP];
    int i = blockIdx.x, head = blockIdx.y;
    int tid = threadIdx.x;                    // 128
    float inv;
    int d = block_softmax(rowptr, colidx, s1[(size_t)head * NN + i],
                          s2 + (size_t)head * NN, i, ex, cj, inv);
    int hw = hid >> 1;
    const __half2* hb = (const __half2*)(h + (size_t)head * NN * hid);
    bool c0 = tid < hw;
    bool c1 = tid + 128 < hw;
    float x0 = 0.f, y0 = 0.f, x1 = 0.f, y1 = 0.f;
#pragma unroll 4
    for (int k = 0; k < d; k++) {
        float a = ex[k];
        const __half2* hr = hb + (size_t)cj[k] * hw;
        if (c0) {
            float2 v = __half22float2(hr[tid]);
            x0 += a * v.x; y0 += a * v.y;
        }
        if (c1) {
            float2 v = __half22float2(hr[tid + 128]);
            x1 += a * v.x; y1 += a * v.y;
        }
    }
    size_t base = (size_t)i * out_stride + (size_t)head * hid;
    if (c0) write_bf_pair(o1, o2, base + 2 * tid, elu1(x0 * inv), elu1(y0 * inv));
    if (c1) write_bf_pair(o1, o2, base + 2 * (tid + 128), elu1(x1 * inv), elu1(y1 * inv));
}

// ---------------- fused output softmax + SpMM: x' = elu(softmax @ ho) ----------------
__global__ void spmm_out_fused(const int* __restrict__ rowptr, const int* __restrict__ colidx,
                               const float* __restrict__ s1, const float* __restrict__ s2,
                               const float* __restrict__ ho,
                               __nv_bfloat16* __restrict__ o1, __nv_bfloat16* __restrict__ o2,
                               float* __restrict__ ofp, int hid) {
    __shared__ float ex[DEG_CAP];
    __shared__ int cj[DEG_CAP];
    int i = blockIdx.x;
    int tid = threadIdx.x;                    // 128
    float inv;
    int d = block_softmax(rowptr, colidx, s1[i], s2, i, ex, cj, inv);
    int hw = hid >> 1;
    bool c0 = tid < hw;
    bool c1 = tid + 128 < hw;
    float x0 = 0.f, y0 = 0.f, x1 = 0.f, y1 = 0.f;
#pragma unroll 4
    for (int k = 0; k < d; k++) {
        float a = ex[k];
        const float2* hr = (const float2*)(ho + (size_t)cj[k] * hid);
        if (c0) {
            float2 v = hr[tid];
            x0 += a * v.x; y0 += a * v.y;
        }
        if (c1) {
            float2 v = hr[tid + 128];
            x1 += a * v.x; y1 += a * v.y;
        }
    }
    size_t base = (size_t)i * hid;
    if (c0) {
        float exv = elu1(x0 * inv), eyv = elu1(y0 * inv);
        if (ofp) *(float2*)(ofp + base + 2 * tid) = make_float2(exv, eyv);
        else     write_bf_pair(o1, o2, base + 2 * tid, exv, eyv);
    }
    if (c1) {
        float exv = elu1(x1 * inv), eyv = elu1(y1 * inv);
        if (ofp) *(float2*)(ofp + base + 2 * (tid + 128)) = make_float2(exv, eyv);
        else     write_bf_pair(o1, o2, base + 2 * (tid + 128), exv, eyv);
    }
}

// ---------------- host side ----------------
struct LayerDims { int fin, hid, fout; };
static const LayerDims g_dims[6] = {
    {256, 128, 128}, {128, 256, 256}, {256, 512, 384},
    {384, 512, 256}, {256, 256, 128}, {128, 128, 256}
};

extern "C" void kernel_launch(void* const* d_in, const int* in_sizes, int n_in,
                              void* d_out, int out_size) {
    const float* x   = (const float*)d_in[0];
    const float* adj = (const float*)d_in[1];

    float *p_s1, *p_s2, *p_ho, *p_o1v, *p_o2v, *p_part;
    int *p_deg, *p_rowptr, *p_colidx;
    __half* p_h;
    __nv_bfloat16 *p_a1, *p_a2, *p_b1, *p_b2;
    cudaGetSymbolAddress((void**)&p_deg, g_deg);
    cudaGetSymbolAddress((void**)&p_rowptr, g_rowptr);
    cudaGetSymbolAddress((void**)&p_colidx, g_colidx);
    cudaGetSymbolAddress((void**)&p_h, g_h);
    cudaGetSymbolAddress((void**)&p_s1, g_s1);
    cudaGetSymbolAddress((void**)&p_s2, g_s2);
    cudaGetSymbolAddress((void**)&p_ho, g_ho);
    cudaGetSymbolAddress((void**)&p_o1v, g_o1);
    cudaGetSymbolAddress((void**)&p_o2v, g_o2);
    cudaGetSymbolAddress((void**)&p_part, g_part);
    cudaGetSymbolAddress((void**)&p_a1, g_a1);
    cudaGetSymbolAddress((void**)&p_a2, g_a2);
    cudaGetSymbolAddress((void**)&p_b1, g_b1);
    cudaGetSymbolAddress((void**)&p_b2, g_b2);

    static int smem_set = 0;
    if (!smem_set) {
        cudaFuncSetAttribute(gemm_mma<float>, cudaFuncAttributeMaxDynamicSharedMemorySize, GSMEM_BYTES);
        cudaFuncSetAttribute(gemm_mma<__half>, cudaFuncAttributeMaxDynamicSharedMemorySize, GSMEM_BYTES);
        smem_set = 1;
    }

    // weight table: offsets into g_b1/g_b2 (in elements), hi/lo split once upfront
    long whoff[6], wooff[6];
    WTab tab;
    long cur = 0, maxN4 = 0;
    for (int l = 0; l < 6; l++) {
        int fin = g_dims[l].fin, hid = g_dims[l].hid, fout = g_dims[l].fout;
        long nWh = (long)NH * fin * hid;
        long nWo = (long)NH * hid * fout;
        whoff[l] = cur;
        tab.e[2 * l] = { (const float*)d_in[2 + 4 * l], cur / 4, nWh / 4 };
        cur += nWh;
        wooff[l] = cur;
        tab.e[2 * l + 1] = { (const float*)d_in[4 + 4 * l], cur / 4, nWo / 4 };
        cur += nWo;
        if (nWh / 4 > maxN4) maxN4 = nWh / 4;
        if (nWo / 4 > maxN4) maxN4 = nWo / 4;
    }

    // Build CSR of adjacency
    csr_count<<<NN / 8, 256>>>(adj, p_deg);
    csr_scan<<<1, 1024>>>(p_deg, p_rowptr);
    csr_fill<<<NN / 8, 256>>>(adj, p_rowptr, p_colidx);

    // all weights split in one launch; layer-0 x split
    split_bf_batch<<<dim3((unsigned)((maxN4 + 255) / 256), 12), 256>>>(tab, p_b1, p_b2);
    split_bf<<<(NN * 256 / 4 + 255) / 256, 256>>>(x, p_a1, p_a2, NN * 256 / 4);

    for (int l = 0; l < 6; l++) {
        int fin = g_dims[l].fin, hid = g_dims[l].hid, fout = g_dims[l].fout;
        const float* ah = (const float*)d_in[3 + 4 * l];
        const float* ao = (const float*)d_in[5 + 4 * l];

        // ---- head GEMM: h[head] = x @ Wh[head], fp16 output ----
        gemm_mma<__half><<<dim3(hid / 128, NN / 128, NH), 256, GSMEM_BYTES>>>(
            p_a1, p_a2, fin, 0L,
            p_b1 + whoff[l], p_b2 + whoff[l], hid, (long)fin * hid,
            p_h, hid, (long)NN * hid, fin);

        // s1/s2, fused softmax+SpMM (writes hcat bf16 hi/lo -> Wo A operands)
        int totalHN = NH * NN;
        dot_s_h<<<(totalHN * 32 + 255) / 256, 256>>>(p_h, ah, p_s1, p_s2, hid, totalHN);
        spmm_h_fused<<<dim3(NN, NH), 128>>>(p_rowptr, p_colidx, p_s1, p_s2, p_h,
                                            p_a1, p_a2, hid, NH * hid);

        // ---- output GEMM: ho = hcat @ Wo, split-K, then fused reduce+dot ----
        int Ktot = NH * hid;
        int Kc = Ktot / KSPLIT;
        gemm_mma<float><<<dim3(fout / 128, NN / 128, KSPLIT), 256, GSMEM_BYTES>>>(
            p_a1, p_a2, Ktot, (long)Kc,
            p_b1 + wooff[l], p_b2 + wooff[l], fout, (long)Kc * fout,
            p_part, fout, (long)NN * fout, Kc);
        reduce_dot<<<NN, 128>>>(p_part, ao, p_ho, p_o1v, p_o2v, fout);

        // fused output softmax + SpMM; fp32 d_out at layer 5, else bf16 hi/lo A
        float* ofp = (l == 5) ? (float*)d_out : nullptr;
        spmm_out_fused<<<NN, 128>>>(p_rowptr, p_colidx, p_o1v, p_o2v, p_ho,
                                    p_a1, p_a2, ofp, fout);
    }
    (void)in_sizes; (void)n_in; (void)out_size;
}

// round 9
// speedup vs baseline: 2.8112x; 1.0587x over previous
#include <cuda_runtime.h>
#include <cuda_bf16.h>
#include <cuda_fp16.h>
#include <math.h>
#include <stdint.h>

#define NN 2048          // nodes
#define NH 8             // heads
#define ALPHA 0.2f
#define NNZ_CAP (2048*128)
#define HID_MAX 512
#define DEG_CAP 1024

// ---------------- scratch (static device allocations) ----------------
__device__ int   g_deg[NN];
__device__ int   g_rowptr[NN + 1];
__device__ int   g_colidx[NNZ_CAP];
__device__ __half g_h[NH * NN * HID_MAX];       // per-head projected features (fp16)
__device__ float g_s1[NH * NN];
__device__ float g_s2[NH * NN];
__device__ __half g_hoh[NN * HID_MAX];          // output-head features (fp16, gather operand)
__device__ float g_o1[NN];
__device__ float g_o2[NN];
__device__ float g_part[8 * NN * 384];          // split-K partials for Wo gemm
// bf16 hi/lo operand buffers (A: activations; B: ALL weights, pre-split once)
__device__ __nv_bfloat16 g_a1[NN * 4096];
__device__ __nv_bfloat16 g_a2[NN * 4096];
__device__ __nv_bfloat16 g_b1[1 << 23];
__device__ __nv_bfloat16 g_b2[1 << 23];

// ---------------- bf16 hi/lo elementwise split ----------------
__device__ __forceinline__ void split4(float4 v, ushort4& uh, ushort4& ul) {
    __nv_bfloat16 h0 = __float2bfloat16_rn(v.x), h1 = __float2bfloat16_rn(v.y);
    __nv_bfloat16 h2 = __float2bfloat16_rn(v.z), h3 = __float2bfloat16_rn(v.w);
    __nv_bfloat16 l0 = __float2bfloat16_rn(v.x - __bfloat162float(h0));
    __nv_bfloat16 l1 = __float2bfloat16_rn(v.y - __bfloat162float(h1));
    __nv_bfloat16 l2 = __float2bfloat16_rn(v.z - __bfloat162float(h2));
    __nv_bfloat16 l3 = __float2bfloat16_rn(v.w - __bfloat162float(h3));
    uh.x = *(unsigned short*)&h0; uh.y = *(unsigned short*)&h1;
    uh.z = *(unsigned short*)&h2; uh.w = *(unsigned short*)&h3;
    ul.x = *(unsigned short*)&l0; ul.y = *(unsigned short*)&l1;
    ul.z = *(unsigned short*)&l2; ul.w = *(unsigned short*)&l3;
}

__global__ void split_bf(const float* __restrict__ in, __nv_bfloat16* __restrict__ o1,
                         __nv_bfloat16* __restrict__ o2, long n4) {
    long i = (long)blockIdx.x * blockDim.x + threadIdx.x;
    if (i >= n4) return;
    ushort4 uh, ul;
    split4(((const float4*)in)[i], uh, ul);
    ((ushort4*)o1)[i] = uh;
    ((ushort4*)o2)[i] = ul;
}

// ---------------- batched weight split ----------------
struct WEnt { const float* src; long off4; long n4; };
struct WTab { WEnt e[12]; };

__global__ void split_bf_batch(WTab tab, __nv_bfloat16* __restrict__ o1,
                               __nv_bfloat16* __restrict__ o2) {
    WEnt en = tab.e[blockIdx.y];
    long i = (long)blockIdx.x * blockDim.x + threadIdx.x;
    if (i >= en.n4) return;
    ushort4 uh, ul;
    split4(((const float4*)en.src)[i], uh, ul);
    ((ushort4*)o1)[en.off4 + i] = uh;
    ((ushort4*)o2)[en.off4 + i] = ul;
}

// ---------------- HMMA bf16x2 GEMM ----------------
#define A_ST 40
#define B_ST 136
#define A_BYTES (128 * A_ST * 2)
#define B_BYTES (32 * B_ST * 2)
#define BUF_BYTES (2 * A_BYTES + 2 * B_BYTES)
#define GSMEM_BYTES (2 * BUF_BYTES)

__device__ __forceinline__ uint32_t smem_u32(const void* p) {
    uint32_t a;
    asm("{ .reg .u64 t; cvta.to.shared.u64 t, %1; cvt.u32.u64 %0, t; }" : "=r"(a) : "l"(p));
    return a;
}

#define LDMX4(r0, r1, r2, r3, addr) \
    asm volatile("ldmatrix.sync.aligned.m8n8.x4.shared.b16 {%0,%1,%2,%3}, [%4];" \
                 : "=r"(r0), "=r"(r1), "=r"(r2), "=r"(r3) : "r"(addr))
#define LDMX2T(r0, r1, addr) \
    asm volatile("ldmatrix.sync.aligned.m8n8.x2.trans.shared.b16 {%0,%1}, [%2];" \
                 : "=r"(r0), "=r"(r1) : "r"(addr))
#define MMA16816(acc, a, b) \
    asm volatile("mma.sync.aligned.m16n8k16.row.col.f32.bf16.bf16.f32 " \
                 "{%0,%1,%2,%3}, {%4,%5,%6,%7}, {%8,%9}, {%0,%1,%2,%3};" \
                 : "+f"((acc)[0]), "+f"((acc)[1]), "+f"((acc)[2]), "+f"((acc)[3]) \
                 : "r"((a)[0]), "r"((a)[1]), "r"((a)[2]), "r"((a)[3]), \
                   "r"((b)[0]), "r"((b)[1]))

__device__ __forceinline__ void store2(float* p, float x, float y) {
    *(float2*)p = make_float2(x, y);
}
__device__ __forceinline__ void store2(__half* p, float x, float y) {
    *(__half2*)p = __floats2half2_rn(x, y);
}

template <typename OT>
__global__ void __launch_bounds__(256, 1) gemm_mma(
    const __nv_bfloat16* __restrict__ A1, const __nv_bfloat16* __restrict__ A2,
    long lda, long sAz,
    const __nv_bfloat16* __restrict__ B1, const __nv_bfloat16* __restrict__ B2,
    long ldb, long sBz,
    OT* __restrict__ C, long ldc, long sCz, int Kc)
{
    extern __shared__ char sm[];
    int tid = threadIdx.x;
    int wid = tid >> 5, lane = tid & 31;
    int mBase = blockIdx.y * 128;
    int nBase = blockIdx.x * 128;
    int z = blockIdx.z;

    const __nv_bfloat16* a1 = A1 + (long)z * sAz + (size_t)mBase * lda;
    const __nv_bfloat16* a2 = A2 + (long)z * sAz + (size_t)mBase * lda;
    const __nv_bfloat16* b1 = B1 + (long)z * sBz + nBase;
    const __nv_bfloat16* b2 = B2 + (long)z * sBz + nBase;
    OT* c = C + (long)z * sCz;

    float acc[4][4][4];
#pragma unroll
    for (int i = 0; i < 4; i++)
#pragma unroll
        for (int j = 0; j < 4; j++)
#pragma unroll
            for (int r = 0; r < 4; r++) acc[i][j][r] = 0.f;

    int mW = (wid >> 2) * 64;
    int nW = (wid & 3) * 32;
    uint32_t sb = smem_u32(sm);
    uint4 ra1[2], ra2[2], rb1[2], rb2[2];

#pragma unroll
    for (int i = 0; i < 2; i++) {
        int cch = i * 256 + tid;
        int r = cch >> 2, ch = cch & 3;
        ra1[i] = *(const uint4*)((const char*)a1 + (size_t)r * lda * 2 + ch * 16);
        ra2[i] = *(const uint4*)((const char*)a2 + (size_t)r * lda * 2 + ch * 16);
        int rB = cch >> 4, chB = cch & 15;
        rb1[i] = *(const uint4*)((const char*)b1 + (size_t)rB * ldb * 2 + chB * 16);
        rb2[i] = *(const uint4*)((const char*)b2 + (size_t)rB * ldb * 2 + chB * 16);
    }
#pragma unroll
    for (int i = 0; i < 2; i++) {
        int cch = i * 256 + tid;
        int r = cch >> 2, ch = cch & 3;
        *(uint4*)(sm + r * (A_ST * 2) + ch * 16) = ra1[i];
        *(uint4*)(sm + A_BYTES + r * (A_ST * 2) + ch * 16) = ra2[i];
        int rB = cch >> 4, chB = cch & 15;
        *(uint4*)(sm + 2 * A_BYTES + rB * (B_ST * 2) + chB * 16) = rb1[i];
        *(uint4*)(sm + 2 * A_BYTES + B_BYTES + rB * (B_ST * 2) + chB * 16) = rb2[i];
    }
    __syncthreads();

    int nT = Kc >> 5;
    for (int t = 0; t < nT; t++) {
        if (t + 1 < nT) {
#pragma unroll
            for (int i = 0; i < 2; i++) {
                int cch = i * 256 + tid;
                int r = cch >> 2, ch = cch & 3;
                ra1[i] = *(const uint4*)((const char*)a1 + (size_t)r * lda * 2 + (t + 1) * 64 + ch * 16);
                ra2[i] = *(const uint4*)((const char*)a2 + (size_t)r * lda * 2 + (t + 1) * 64 + ch * 16);
                int rB = cch >> 4, chB = cch & 15;
                rb1[i] = *(const uint4*)((const char*)b1 + (size_t)((t + 1) * 32 + rB) * ldb * 2 + chB * 16);
                rb2[i] = *(const uint4*)((const char*)b2 + (size_t)((t + 1) * 32 + rB) * ldb * 2 + chB * 16);
            }
        }
        uint32_t bufb = sb + (uint32_t)(t & 1) * BUF_BYTES;
        uint32_t sA1 = bufb;
        uint32_t sA2 = bufb + A_BYTES;
        uint32_t sB1 = bufb + 2 * A_BYTES;
        uint32_t sB2 = bufb + 2 * A_BYTES + B_BYTES;

#pragma unroll
        for (int kk = 0; kk < 32; kk += 16) {
            uint32_t af[2][4][4];
            uint32_t bfr[2][4][2];
#pragma unroll
            for (int mt = 0; mt < 4; mt++) {
                uint32_t off = (uint32_t)((mW + mt * 16 + (lane & 15)) * (A_ST * 2)
                                          + (kk + ((lane >> 4) << 3)) * 2);
                LDMX4(af[0][mt][0], af[0][mt][1], af[0][mt][2], af[0][mt][3], sA1 + off);
                LDMX4(af[1][mt][0], af[1][mt][1], af[1][mt][2], af[1][mt][3], sA2 + off);
            }
#pragma unroll
            for (int nt = 0; nt < 4; nt++) {
                uint32_t off = (uint32_t)((kk + (lane & 15)) * (B_ST * 2) + (nW + nt * 8) * 2);
                LDMX2T(bfr[0][nt][0], bfr[0][nt][1], sB1 + off);
                LDMX2T(bfr[1][nt][0], bfr[1][nt][1], sB2 + off);
            }
#pragma unroll
            for (int mt = 0; mt < 4; mt++)
#pragma unroll
                for (int nt = 0; nt < 4; nt++) {
                    MMA16816(acc[mt][nt], af[0][mt], bfr[0][nt]);
                    MMA16816(acc[mt][nt], af[0][mt], bfr[1][nt]);
                    MMA16816(acc[mt][nt], af[1][mt], bfr[0][nt]);
                }
        }
        if (t + 1 < nT) {
            char* nb = sm + ((t + 1) & 1) * BUF_BYTES;
#pragma unroll
            for (int i = 0; i < 2; i++) {
                int cch = i * 256 + tid;
                int r = cch >> 2, ch = cch & 3;
                *(uint4*)(nb + r * (A_ST * 2) + ch * 16) = ra1[i];
                *(uint4*)(nb + A_BYTES + r * (A_ST * 2) + ch * 16) = ra2[i];
                int rB = cch >> 4, chB = cch & 15;
                *(uint4*)(nb + 2 * A_BYTES + rB * (B_ST * 2) + chB * 16) = rb1[i];
                *(uint4*)(nb + 2 * A_BYTES + B_BYTES + rB * (B_ST * 2) + chB * 16) = rb2[i];
            }
            __syncthreads();
        }
    }

#pragma unroll
    for (int mt = 0; mt < 4; mt++) {
        int row0 = mBase + mW + mt * 16 + (lane >> 2);
#pragma unroll
        for (int nt = 0; nt < 4; nt++) {
            int col = nBase + nW + nt * 8 + (lane & 3) * 2;
            OT* cr = c + (size_t)row0 * ldc + col;
            store2(cr, acc[mt][nt][0], acc[mt][nt][1]);
            store2(cr + 8 * ldc, acc[mt][nt][2], acc[mt][nt][3]);
        }
    }
}

// ---------------- CSR build ----------------
__global__ void csr_count(const float* __restrict__ adj, int* __restrict__ deg) {
    int row = blockIdx.x * (blockDim.x >> 5) + (threadIdx.x >> 5);
    if (row >= NN) return;
    int lane = threadIdx.x & 31;
    const float* r = adj + (size_t)row * NN;
    int cnt = 0;
    for (int c0 = 0; c0 < NN; c0 += 32) {
        float v = r[c0 + lane];
        unsigned m = __ballot_sync(0xffffffffu, v > 0.f);
        cnt += __popc(m);
    }
    if (lane == 0) deg[row] = cnt;
}

__global__ void csr_scan(const int* __restrict__ deg, int* __restrict__ rowptr) {
    __shared__ int s[1024];
    int t = threadIdx.x;
    int d0 = deg[2 * t], d1 = deg[2 * t + 1];
    s[t] = d0 + d1;
    __syncthreads();
    for (int off = 1; off < 1024; off <<= 1) {
        int v = s[t];
        int add = (t >= off) ? s[t - off] : 0;
        __syncthreads();
        s[t] = v + add;
        __syncthreads();
    }
    int excl = (t > 0) ? s[t - 1] : 0;
    rowptr[2 * t]     = excl;
    rowptr[2 * t + 1] = excl + d0;
    if (t == 1023) rowptr[NN] = s[1023];
}

__global__ void csr_fill(const float* __restrict__ adj, const int* __restrict__ rowptr,
                         int* __restrict__ colidx) {
    int row = blockIdx.x * (blockDim.x >> 5) + (threadIdx.x >> 5);
    if (row >= NN) return;
    int lane = threadIdx.x & 31;
    const float* r = adj + (size_t)row * NN;
    int pos = rowptr[row];
    for (int c0 = 0; c0 < NN; c0 += 32) {
        float v = r[c0 + lane];
        unsigned m = __ballot_sync(0xffffffffu, v > 0.f);
        if (v > 0.f) {
            int off = __popc(m & ((1u << lane) - 1u));
            colidx[pos + off] = c0 + lane;
        }
        pos += __popc(m);
    }
}

// ---------------- s1/s2 dot products (half h) ----------------
__global__ void dot_s_h(const __half* __restrict__ h, const float* __restrict__ a,
                        float* __restrict__ s1, float* __restrict__ s2, int hid, int total) {
    int w = (blockIdx.x * blockDim.x + threadIdx.x) >> 5;
    if (w >= total) return;
    int lane = threadIdx.x & 31;
    int head = w / NN;
    const __half2* hp = (const __half2*)(h + (size_t)w * hid);
    const float* a1 = a + (size_t)head * 2 * hid;
    const float* a2 = a1 + hid;
    int hw = hid >> 1;
    float v1 = 0.f, v2 = 0.f;
    for (int d = lane; d < hw; d += 32) {
        float2 x = __half22float2(hp[d]);
        float2 w1 = *(const float2*)&a1[2 * d];
        float2 w2 = *(const float2*)&a2[2 * d];
        v1 += x.x * w1.x + x.y * w1.y;
        v2 += x.x * w2.x + x.y * w2.y;
    }
#pragma unroll
    for (int o = 16; o; o >>= 1) {
        v1 += __shfl_xor_sync(0xffffffffu, v1, o);
        v2 += __shfl_xor_sync(0xffffffffu, v2, o);
    }
    if (lane == 0) { s1[w] = v1; s2[w] = v2; }
}

// ---------------- fused split-K reduce + o1/o2 dot (block per node) ----------------
// fp32 partial sums and exact fp32 dots; fp16 stored gather operand.
__global__ void reduce_dot(const float* __restrict__ part, const float* __restrict__ ao,
                           __half* __restrict__ hoh, float* __restrict__ o1,
                           float* __restrict__ o2, int fout, int ks) {
    __shared__ float rbuf[8];
    int i = blockIdx.x;
    int tid = threadIdx.x;                  // 128
    int wid = tid >> 5, lane = tid & 31;
    size_t MN = (size_t)NN * fout;
    float v1 = 0.f, v2 = 0.f;
    for (int c = tid; c < fout; c += 128) {
        size_t idx = (size_t)i * fout + c;
        float s = 0.f;
        for (int p = 0; p < ks; p++) s += part[(size_t)p * MN + idx];
        hoh[idx] = __float2half_rn(s);
        v1 += s * ao[c];
        v2 += s * ao[fout + c];
    }
#pragma unroll
    for (int o = 16; o; o >>= 1) {
        v1 += __shfl_xor_sync(0xffffffffu, v1, o);
        v2 += __shfl_xor_sync(0xffffffffu, v2, o);
    }
    if (lane == 0) { rbuf[wid] = v1; rbuf[4 + wid] = v2; }
    __syncthreads();
    if (tid == 0) {
        o1[i] = rbuf[0] + rbuf[1] + rbuf[2] + rbuf[3];
        o2[i] = rbuf[4] + rbuf[5] + rbuf[6] + rbuf[7];
    }
}

// ---------------- helpers ----------------
__device__ __forceinline__ float elu1(float x) { return x > 0.f ? x : expm1f(x); }

__device__ __forceinline__ ushort4 bf_hi4(float a, float b, float c, float d,
                                          float& ra, float& rb, float& rc, float& rd) {
    __nv_bfloat16 ha = __float2bfloat16_rn(a), hb = __float2bfloat16_rn(b);
    __nv_bfloat16 hc = __float2bfloat16_rn(c), hd = __float2bfloat16_rn(d);
    ra = a - __bfloat162float(ha); rb = b - __bfloat162float(hb);
    rc = c - __bfloat162float(hc); rd = d - __bfloat162float(hd);
    ushort4 u;
    u.x = *(unsigned short*)&ha; u.y = *(unsigned short*)&hb;
    u.z = *(unsigned short*)&hc; u.w = *(unsigned short*)&hd;
    return u;
}
__device__ __forceinline__ ushort4 bf_lo4(float a, float b, float c, float d) {
    __nv_bfloat16 la = __float2bfloat16_rn(a), lb = __float2bfloat16_rn(b);
    __nv_bfloat16 lc = __float2bfloat16_rn(c), ld = __float2bfloat16_rn(d);
    ushort4 u;
    u.x = *(unsigned short*)&la; u.y = *(unsigned short*)&lb;
    u.z = *(unsigned short*)&lc; u.w = *(unsigned short*)&ld;
    return u;
}
__device__ __forceinline__ void write_bf_quad(__nv_bfloat16* o1, __nv_bfloat16* o2,
                                              size_t idx, float a, float b, float c, float d) {
    float ra, rb, rc, rd;
    *(ushort4*)(o1 + idx) = bf_hi4(a, b, c, d, ra, rb, rc, rd);
    *(ushort4*)(o2 + idx) = bf_lo4(ra, rb, rc, rd);
}

// block softmax over neighbor list. 128 threads.
__device__ __forceinline__ int block_softmax(const int* __restrict__ rowptr,
                                             const int* __restrict__ colidx,
                                             float si, const float* __restrict__ s2,
                                             int i, float* ex, int* cj, float& inv) {
    __shared__ float rbuf[8];
    int tid = threadIdx.x;
    int wid = tid >> 5, lane = tid & 31;
    int b = rowptr[i];
    int d = rowptr[i + 1] - b;
    if (d > DEG_CAP) d = DEG_CAP;
    float lm = -1e30f;
    for (int k = tid; k < d; k += 128) {
        int j = colidx[b + k];
        cj[k] = j;
        float v = si + s2[j];
        v = v > 0.f ? v : ALPHA * v;
        ex[k] = v;
        lm = fmaxf(lm, v);
    }
#pragma unroll
    for (int o = 16; o; o >>= 1) lm = fmaxf(lm, __shfl_xor_sync(0xffffffffu, lm, o));
    if (lane == 0) rbuf[wid] = lm;
    __syncthreads();
    float m = fmaxf(fmaxf(rbuf[0], rbuf[1]), fmaxf(rbuf[2], rbuf[3]));
    float ls = 0.f;
    for (int k = tid; k < d; k += 128) {
        float t = expf(ex[k] - m);
        ex[k] = t;
        ls += t;
    }
#pragma unroll
    for (int o = 16; o; o >>= 1) ls += __shfl_xor_sync(0xffffffffu, ls, o);
    if (lane == 0) rbuf[4 + wid] = ls;
    __syncthreads();
    inv = 1.f / (rbuf[4] + rbuf[5] + rbuf[6] + rbuf[7]);
    return d;
}

__device__ __forceinline__ void unpack_h4(uint2 v, float& a, float& b, float& c, float& d) {
    float2 p0 = __half22float2(*(__half2*)&v.x);
    float2 p1 = __half22float2(*(__half2*)&v.y);
    a = p0.x; b = p0.y; c = p1.x; d = p1.y;
}

// ---------------- fused head softmax + SpMM: hcat = elu(softmax @ h) ----------------
// 8B-vectorized gather: thread covers 4 half values; hid/4 <= 128.
__global__ void spmm_h_fused(const int* __restrict__ rowptr, const int* __restrict__ colidx,
                             const float* __restrict__ s1, const float* __restrict__ s2,
                             const __half* __restrict__ h,
                             __nv_bfloat16* __restrict__ o1, __nv_bfloat16* __restrict__ o2,
                             int hid, int out_stride) {
    __shared__ float ex[DEG_CAP];
    __shared__ int cj[DEG_CAP];
    int i = blockIdx.x, head = blockIdx.y;
    int tid = threadIdx.x;                    // 128
    float inv;
    int d = block_softmax(rowptr, colidx, s1[(size_t)head * NN + i],
                          s2 + (size_t)head * NN, i, ex, cj, inv);
    int pos = hid >> 2;                       // uint2 chunks per row (32..128)
    if (tid >= pos) return;
    const uint2* hb = (const uint2*)(h + (size_t)head * NN * hid);
    float x0 = 0.f, x1 = 0.f, x2 = 0.f, x3 = 0.f;
#pragma unroll 4
    for (int k = 0; k < d; k++) {
        float a = ex[k];
        float v0, v1, v2, v3;
        unpack_h4(hb[(size_t)cj[k] * pos + tid], v0, v1, v2, v3);
        x0 += a * v0; x1 += a * v1; x2 += a * v2; x3 += a * v3;
    }
    size_t base = (size_t)i * out_stride + (size_t)head * hid + 4 * tid;
    write_bf_quad(o1, o2, base, elu1(x0 * inv), elu1(x1 * inv), elu1(x2 * inv), elu1(x3 * inv));
}

// ---------------- fused output softmax + SpMM: x' = elu(softmax @ ho_fp16) ----------------
__global__ void spmm_out_fused(const int* __restrict__ rowptr, const int* __restrict__ colidx,
                               const float* __restrict__ s1, const float* __restrict__ s2,
                               const __half* __restrict__ hoh,
                               __nv_bfloat16* __restrict__ o1, __nv_bfloat16* __restrict__ o2,
                               float* __restrict__ ofp, int hid) {
    __shared__ float ex[DEG_CAP];
    __shared__ int cj[DEG_CAP];
    int i = blockIdx.x;
    int tid = threadIdx.x;                    // 128
    float inv;
    int d = block_softmax(rowptr, colidx, s1[i], s2, i, ex, cj, inv);
    int pos = hid >> 2;                       // 32..96
    if (tid >= pos) return;
    const uint2* hb = (const uint2*)hoh;
    float x0 = 0.f, x1 = 0.f, x2 = 0.f, x3 = 0.f;
#pragma unroll 4
    for (int k = 0; k < d; k++) {
        float a = ex[k];
        float v0, v1, v2, v3;
        unpack_h4(hb[(size_t)cj[k] * pos + tid], v0, v1, v2, v3);
        x0 += a * v0; x1 += a * v1; x2 += a * v2; x3 += a * v3;
    }
    float e0 = elu1(x0 * inv), e1 = elu1(x1 * inv), e2 = elu1(x2 * inv), e3 = elu1(x3 * inv);
    size_t base = (size_t)i * hid + 4 * tid;
    if (ofp) *(float4*)(ofp + base) = make_float4(e0, e1, e2, e3);
    else     write_bf_quad(o1, o2, base, e0, e1, e2, e3);
}

// ---------------- host side ----------------
struct LayerDims { int fin, hid, fout; };
static const LayerDims g_dims[6] = {
    {256, 128, 128}, {128, 256, 256}, {256, 512, 384},
    {384, 512, 256}, {256, 256, 128}, {128, 128, 256}
};

extern "C" void kernel_launch(void* const* d_in, const int* in_sizes, int n_in,
                              void* d_out, int out_size) {
    const float* x   = (const float*)d_in[0];
    const float* adj = (const float*)d_in[1];

    float *p_s1, *p_s2, *p_o1v, *p_o2v, *p_part;
    int *p_deg, *p_rowptr, *p_colidx;
    __half *p_h, *p_hoh;
    __nv_bfloat16 *p_a1, *p_a2, *p_b1, *p_b2;
    cudaGetSymbolAddress((void**)&p_deg, g_deg);
    cudaGetSymbolAddress((void**)&p_rowptr, g_rowptr);
    cudaGetSymbolAddress((void**)&p_colidx, g_colidx);
    cudaGetSymbolAddress((void**)&p_h, g_h);
    cudaGetSymbolAddress((void**)&p_s1, g_s1);
    cudaGetSymbolAddress((void**)&p_s2, g_s2);
    cudaGetSymbolAddress((void**)&p_hoh, g_hoh);
    cudaGetSymbolAddress((void**)&p_o1v, g_o1);
    cudaGetSymbolAddress((void**)&p_o2v, g_o2);
    cudaGetSymbolAddress((void**)&p_part, g_part);
    cudaGetSymbolAddress((void**)&p_a1, g_a1);
    cudaGetSymbolAddress((void**)&p_a2, g_a2);
    cudaGetSymbolAddress((void**)&p_b1, g_b1);
    cudaGetSymbolAddress((void**)&p_b2, g_b2);

    static int smem_set = 0;
    if (!smem_set) {
        cudaFuncSetAttribute(gemm_mma<float>, cudaFuncAttributeMaxDynamicSharedMemorySize, GSMEM_BYTES);
        cudaFuncSetAttribute(gemm_mma<__half>, cudaFuncAttributeMaxDynamicSharedMemorySize, GSMEM_BYTES);
        smem_set = 1;
    }

    // weight table: offsets into g_b1/g_b2 (elements), hi/lo split once upfront
    long whoff[6], wooff[6];
    WTab tab;
    long cur = 0, maxN4 = 0;
    for (int l = 0; l < 6; l++) {
        int fin = g_dims[l].fin, hid = g_dims[l].hid, fout = g_dims[l].fout;
        long nWh = (long)NH * fin * hid;
        long nWo = (long)NH * hid * fout;
        whoff[l] = cur;
        tab.e[2 * l] = { (const float*)d_in[2 + 4 * l], cur / 4, nWh / 4 };
        cur += nWh;
        wooff[l] = cur;
        tab.e[2 * l + 1] = { (const float*)d_in[4 + 4 * l], cur / 4, nWo / 4 };
        cur += nWo;
        if (nWh / 4 > maxN4) maxN4 = nWh / 4;
        if (nWo / 4 > maxN4) maxN4 = nWo / 4;
    }

    // Build CSR of adjacency
    csr_count<<<NN / 8, 256>>>(adj, p_deg);
    csr_scan<<<1, 1024>>>(p_deg, p_rowptr);
    csr_fill<<<NN / 8, 256>>>(adj, p_rowptr, p_colidx);

    // all weights split in one launch; layer-0 x split
    split_bf_batch<<<dim3((unsigned)((maxN4 + 255) / 256), 12), 256>>>(tab, p_b1, p_b2);
    split_bf<<<(NN * 256 / 4 + 255) / 256, 256>>>(x, p_a1, p_a2, NN * 256 / 4);

    for (int l = 0; l < 6; l++) {
        int fin = g_dims[l].fin, hid = g_dims[l].hid, fout = g_dims[l].fout;
        const float* ah = (const float*)d_in[3 + 4 * l];
        const float* ao = (const float*)d_in[5 + 4 * l];

        // ---- head GEMM: h[head] = x @ Wh[head], fp16 output ----
        gemm_mma<__half><<<dim3(hid / 128, NN / 128, NH), 256, GSMEM_BYTES>>>(
            p_a1, p_a2, fin, 0L,
            p_b1 + whoff[l], p_b2 + whoff[l], hid, (long)fin * hid,
            p_h, hid, (long)NN * hid, fin);

        // s1/s2, fused softmax+SpMM (writes hcat bf16 hi/lo -> Wo A operands)
        int totalHN = NH * NN;
        dot_s_h<<<(totalHN * 32 + 255) / 256, 256>>>(p_h, ah, p_s1, p_s2, hid, totalHN);
        spmm_h_fused<<<dim3(NN, NH), 128>>>(p_rowptr, p_colidx, p_s1, p_s2, p_h,
                                            p_a1, p_a2, hid, NH * hid);

        // ---- output GEMM: ho = hcat @ Wo, adaptive split-K, fused reduce+dot ----
        int Ktot = NH * hid;
        int ks = (fout >= 256) ? 4 : 8;
        int Kc = Ktot / ks;
        gemm_mma<float><<<dim3(fout / 128, NN / 128, ks), 256, GSMEM_BYTES>>>(
            p_a1, p_a2, Ktot, (long)Kc,
            p_b1 + wooff[l], p_b2 + wooff[l], fout, (long)Kc * fout,
            p_part, fout, (long)NN * fout, Kc);
        reduce_dot<<<NN, 128>>>(p_part, ao, p_hoh, p_o1v, p_o2v, fout, ks);

        // fused output softmax + SpMM; fp32 d_out at layer 5, else bf16 hi/lo A
        float* ofp = (l == 5) ? (float*)d_out : nullptr;
        spmm_out_fused<<<NN, 128>>>(p_rowptr, p_colidx, p_o1v, p_o2v, p_hoh,
                                    p_a1, p_a2, ofp, fout);
    }
    (void)in_sizes; (void)n_in; (void)out_size;
}